// round 4
// baseline (speedup 1.0000x reference)
#include <cuda_runtime.h>
#include <math.h>

#define BSZ 32
#define NXS 16384
#define IN_DIM 3
#define DIMC 64
#define NJ 16
#define MODE 128
#define RANKR 4
#define FCD 128
#define N_LAYERS 3

#define XH_SPLITS 32
#define Y_SPLITS 8
#define T_SPLITS 8

// ---------------- scratch (device globals; no allocations) ----------------
__device__ float g_h [BSZ*DIMC*NXS];                 // 128 MB (h after layer0)
__device__ float g_h2[BSZ*DIMC*NXS];                 // 128 MB (h after layer1)
__device__ float g_basesT[MODE*NXS];                 // 8 MB
__device__ float g_xT[BSZ*IN_DIM*NXS];               // x transposed (b,d,x)
__device__ float g_HT[NJ*MODE*MODE];                 // H^T: [j][l][k]
__device__ float g_xh [BSZ*DIMC*MODE];               // (b,c,k)
__device__ float g_xhp[XH_SPLITS*BSZ*DIMC*MODE];     // split partials
__device__ float g_xh1[BSZ*DIMC*NJ*MODE];            // (b, c*16+j, k)
__device__ float g_WrT[NJ*DIMC*DIMC];                // (p=i*16+j, o)
__device__ float g_y  [BSZ*DIMC*MODE];
__device__ float g_yp [Y_SPLITS*BSZ*DIMC*MODE];
__device__ float g_Tp [T_SPLITS*BSZ*4*MODE];         // partial T (d=3 row: colsum wbases)
__device__ float g_Wc0T[IN_DIM*DIMC];                // (d, o): W_conv0 @ W0^T transposed
__device__ float g_bias0[DIMC];

__device__ __forceinline__ float gelu_f(float v){
    return 0.5f * v * (1.0f + erff(v * 0.70710678118654752440f));
}

// ---------------- bases transpose: basesT[k][x] = bases[x][k] -------------
__global__ void k_transpose(const float* __restrict__ bases){
    __shared__ float t[32][33];
    int x0 = blockIdx.x * 32, k0 = blockIdx.y * 32;
    for (int i = threadIdx.y; i < 32; i += 8)
        t[i][threadIdx.x] = bases[(size_t)(x0 + i) * MODE + k0 + threadIdx.x];
    __syncthreads();
    for (int i = threadIdx.y; i < 32; i += 8)
        g_basesT[(size_t)(k0 + i) * NXS + x0 + threadIdx.x] = t[threadIdx.x][i];
}

// ---------------- x transpose: xT[b][d][x] = x[b][x][d] --------------------
__global__ void k_xT(const float* __restrict__ x){
    int i = blockIdx.x * 256 + threadIdx.x;     // < 32*16384*3
    int d = i % 3;
    int t = i / 3;
    int xp = t & (NXS-1);
    int b  = t >> 14;
    g_xT[((size_t)b*IN_DIM + d)*NXS + xp] = x[i];
}

// ---------------- H^T build: HT[j][l][k] = H[j][k][l] ----------------------
__global__ void k_buildHT(const float* __restrict__ Do, const float* __restrict__ Di,
                          const float* __restrict__ pr, const float* __restrict__ A,
                          const float* __restrict__ Bm){
    int j = blockIdx.x, l = blockIdx.y, k = threadIdx.x;
    float s = Do[j*MODE + k] * Di[j*MODE + l] * pr[k*MODE + l];
    #pragma unroll
    for (int r = 0; r < RANKR; r++)
        s += A[(j*RANKR + r)*MODE + k] * Bm[(j*RANKR + r)*MODE + l];
    g_HT[((size_t)j*MODE + l)*MODE + k] = s;
}

// ------- layer-0 prep: Wc0T[d][o] = sum_c W_conv[0,o,c] W0[d,c];  bias0 ----
__global__ void k_prep0(const float* __restrict__ W_conv, const float* __restrict__ W0,
                        const float* __restrict__ b0, const float* __restrict__ b_conv){
    int o = threadIdx.x;   // 64 threads
    float w0s = 0.f, w1s = 0.f, w2s = 0.f, bb = b_conv[o];
    for (int c = 0; c < DIMC; c++){
        float wc = W_conv[o*DIMC + c];
        w0s += wc * W0[0*DIMC + c];
        w1s += wc * W0[1*DIMC + c];
        w2s += wc * W0[2*DIMC + c];
        bb  += wc * b0[c];
    }
    g_Wc0T[0*DIMC + o] = w0s;
    g_Wc0T[1*DIMC + o] = w1s;
    g_Wc0T[2*DIMC + o] = w2s;
    g_bias0[o] = bb;
}

// ------- layer-0 T partials: Tp[s,b,d,k] = sum_{x in split} xT[b,d,x] wb[x,k]
//         (d=3 slot accumulates sum of wbases, for the b0 term)
__global__ void k_T(const float* __restrict__ wbases){
    int b = blockIdx.x, s = blockIdx.y;
    int x0 = s * (NXS / T_SPLITS);       // 2048 chunk
    int k = threadIdx.x;                 // 128 threads
    __shared__ float xs[3][128];
    float a0 = 0.f, a1 = 0.f, a2 = 0.f, a3 = 0.f;
    for (int xt = 0; xt < (NXS/T_SPLITS)/128; xt++){
        __syncthreads();
        xs[0][k] = g_xT[((size_t)b*IN_DIM + 0)*NXS + x0 + xt*128 + k];
        xs[1][k] = g_xT[((size_t)b*IN_DIM + 1)*NXS + x0 + xt*128 + k];
        xs[2][k] = g_xT[((size_t)b*IN_DIM + 2)*NXS + x0 + xt*128 + k];
        __syncthreads();
        #pragma unroll 8
        for (int xi = 0; xi < 128; xi++){
            float w = wbases[(size_t)(x0 + xt*128 + xi)*MODE + k];
            a0 += xs[0][xi] * w;
            a1 += xs[1][xi] * w;
            a2 += xs[2][xi] * w;
            a3 += w;
        }
    }
    size_t base = (((size_t)s*BSZ + b)*4)*MODE + k;
    g_Tp[base + 0*MODE] = a0;
    g_Tp[base + 1*MODE] = a1;
    g_Tp[base + 2*MODE] = a2;
    g_Tp[base + 3*MODE] = a3;
}

// ------- layer-0 xh: xh0[b,c,k] = sum_d W0[d,c] T[b,d,k] + b0[c]*S[k] ------
__global__ void k_xh0(const float* __restrict__ W0, const float* __restrict__ b0){
    int b = blockIdx.x;
    __shared__ float Ts[4][128];
    int tid = threadIdx.x;
    for (int e = tid; e < 4*MODE; e += 256){
        int d = e >> 7, k = e & 127;
        float s = 0.f;
        #pragma unroll
        for (int s8 = 0; s8 < T_SPLITS; s8++)
            s += g_Tp[(((size_t)s8*BSZ + b)*4 + d)*MODE + k];
        Ts[d][k] = s;
    }
    __syncthreads();
    for (int o = tid; o < DIMC*MODE; o += 256){
        int c = o >> 7, k = o & 127;
        float v = W0[0*DIMC + c]*Ts[0][k] + W0[1*DIMC + c]*Ts[1][k]
                + W0[2*DIMC + c]*Ts[2][k] + b0[c]*Ts[3][k];
        g_xh[((size_t)b*DIMC + c)*MODE + k] = v;
    }
}

// ---------------- xh split-K GEMM (layers 1,2): 128x128 tile ---------------
// xh[m,k] = sum_x h[m,x] wbases[x,k],  m = b*64+c  (2048 rows)
__global__ void __launch_bounds__(256) k_xh_part(const float* __restrict__ hin,
                                                 const float* __restrict__ wbases){
    int m0 = blockIdx.x * 128;
    int split = blockIdx.y;
    int k0 = split * (NXS / XH_SPLITS);     // 512 chunk
    __shared__ float As[16][136];           // [kk][row], row-dim contiguous
    __shared__ float Bs[16][128];
    int tid = threadIdx.x;
    int ty = tid >> 4, tx = tid & 15;       // 16x16 thread grid, 8x8 each
    float acc[8][8] = {};
    int ar = tid >> 2, aq = tid & 3;        // A staging: rows ar, ar+64; k-quad aq
    int br = tid >> 5, bc = tid & 31;       // B staging: rows br, br+8
    for (int kt = 0; kt < (NXS/XH_SPLITS)/16; kt++){
        int kg = k0 + kt*16;
        float4 a0 = *(const float4*)&hin[(size_t)(m0 + ar)*NXS + kg + aq*4];
        float4 a1 = *(const float4*)&hin[(size_t)(m0 + ar + 64)*NXS + kg + aq*4];
        float4 b0v = *(const float4*)&wbases[(size_t)(kg + br)*MODE + bc*4];
        float4 b1v = *(const float4*)&wbases[(size_t)(kg + br + 8)*MODE + bc*4];
        __syncthreads();
        As[aq*4+0][ar] = a0.x; As[aq*4+1][ar] = a0.y;
        As[aq*4+2][ar] = a0.z; As[aq*4+3][ar] = a0.w;
        As[aq*4+0][ar+64] = a1.x; As[aq*4+1][ar+64] = a1.y;
        As[aq*4+2][ar+64] = a1.z; As[aq*4+3][ar+64] = a1.w;
        *(float4*)&Bs[br][bc*4] = b0v;
        *(float4*)&Bs[br+8][bc*4] = b1v;
        __syncthreads();
        #pragma unroll
        for (int kk = 0; kk < 16; kk++){
            float a[8], b[8];
            *(float4*)&a[0] = *(const float4*)&As[kk][ty*8];
            *(float4*)&a[4] = *(const float4*)&As[kk][ty*8+4];
            *(float4*)&b[0] = *(const float4*)&Bs[kk][tx*8];
            *(float4*)&b[4] = *(const float4*)&Bs[kk][tx*8+4];
            #pragma unroll
            for (int i = 0; i < 8; i++)
                #pragma unroll
                for (int j = 0; j < 8; j++)
                    acc[i][j] += a[i]*b[j];
        }
    }
    float* dst = &g_xhp[(size_t)split*(BSZ*DIMC*MODE)];
    #pragma unroll
    for (int i = 0; i < 8; i++){
        int m = m0 + ty*8 + i;
        *(float4*)&dst[(size_t)m*MODE + tx*8]     = make_float4(acc[i][0],acc[i][1],acc[i][2],acc[i][3]);
        *(float4*)&dst[(size_t)m*MODE + tx*8 + 4] = make_float4(acc[i][4],acc[i][5],acc[i][6],acc[i][7]);
    }
}

__global__ void k_reduce_xh(){
    int i = blockIdx.x * 256 + threadIdx.x;   // < 262144
    float s = 0.f;
    #pragma unroll
    for (int k = 0; k < XH_SPLITS; k++) s += g_xhp[(size_t)k*(BSZ*DIMC*MODE) + i];
    g_xh[i] = s;
}

// ---------------- xh1[b, c*16+j, k] = sum_l xh[b,c,l] * HT[j,l,k] ----------
__global__ void __launch_bounds__(256) k_xh1(){
    int b = blockIdx.x, j = blockIdx.y;
    __shared__ float xs[64][128];
    __shared__ float Bs[16][128];
    int tid = threadIdx.x, rg = tid >> 5, cg = tid & 31;
    {
        const float4* src = (const float4*)&g_xh[(size_t)b*DIMC*MODE];
        float4* dst = (float4*)&xs[0][0];
        for (int i = tid; i < 64*128/4; i += 256) dst[i] = src[i];
    }
    float acc[8][4] = {};
    for (int kt = 0; kt < 8; kt++){
        int kkB = tid >> 4, n8 = (tid & 15) * 8;
        const float* bsrc = &g_HT[((size_t)j*MODE + kt*16 + kkB)*MODE + n8];
        float4 bv0 = *(const float4*)bsrc, bv1 = *(const float4*)(bsrc + 4);
        __syncthreads();
        *(float4*)&Bs[kkB][n8] = bv0; *(float4*)&Bs[kkB][n8+4] = bv1;
        __syncthreads();
        #pragma unroll
        for (int kk = 0; kk < 16; kk++){
            int l = kt*16 + kk;
            float a_[8];
            #pragma unroll
            for (int i_ = 0; i_ < 8; i_++) a_[i_] = xs[rg*8 + i_][l];
            float4 bv_ = *(const float4*)&Bs[kk][cg*4];
            #pragma unroll
            for (int i_ = 0; i_ < 8; i_++){
                acc[i_][0] += a_[i_]*bv_.x; acc[i_][1] += a_[i_]*bv_.y;
                acc[i_][2] += a_[i_]*bv_.z; acc[i_][3] += a_[i_]*bv_.w;
            }
        }
    }
    #pragma unroll
    for (int i = 0; i < 8; i++){
        float4 v = make_float4(acc[i][0],acc[i][1],acc[i][2],acc[i][3]);
        *(float4*)&g_xh1[((size_t)b*(DIMC*NJ) + (size_t)(rg*8 + i)*NJ + j)*MODE + cg*4] = v;
    }
}

// ---------------- W_sp reorder: WrT[p][o] = W_sp[li, i, o, j], p=i*16+j ----
__global__ void k_WrT(const float* __restrict__ W_sp, int li){
    int idx = blockIdx.x * 256 + threadIdx.x;  // < 65536
    int o = idx & 63, p = idx >> 6;
    int i = p >> 4, jj = p & 15;
    g_WrT[(size_t)p*DIMC + o] = W_sp[(((size_t)li*DIMC + i)*DIMC + o)*NJ + jj];
}

// ---------------- y split-K GEMM: y[b,o,k] = sum_p WrT[p,o] xh1[b,p,k] -----
__global__ void __launch_bounds__(256) k_y_part(){
    int b = blockIdx.x, s = blockIdx.y;
    int p0 = s * 128;
    __shared__ float As[16][65];
    __shared__ float Bs[16][128];
    int tid = threadIdx.x, rg = tid >> 5, cg = tid & 31;
    float acc[8][4] = {};
    for (int kt = 0; kt < 8; kt++){
        int kkA = tid >> 4, o4 = (tid & 15) * 4;
        float4 av = *(const float4*)&g_WrT[(size_t)(p0 + kt*16 + kkA)*DIMC + o4];
        int kkB = tid >> 4, n8 = (tid & 15) * 8;
        const float* bsrc = &g_xh1[((size_t)b*(DIMC*NJ) + p0 + kt*16 + kkB)*MODE + n8];
        float4 bv0 = *(const float4*)bsrc, bv1 = *(const float4*)(bsrc + 4);
        __syncthreads();
        As[kkA][o4+0]=av.x; As[kkA][o4+1]=av.y; As[kkA][o4+2]=av.z; As[kkA][o4+3]=av.w;
        *(float4*)&Bs[kkB][n8] = bv0; *(float4*)&Bs[kkB][n8+4] = bv1;
        __syncthreads();
        #pragma unroll
        for (int kk = 0; kk < 16; kk++){
            float a_[8];
            #pragma unroll
            for (int i_ = 0; i_ < 8; i_++) a_[i_] = As[kk][rg*8 + i_];
            float4 bv_ = *(const float4*)&Bs[kk][cg*4];
            #pragma unroll
            for (int i_ = 0; i_ < 8; i_++){
                acc[i_][0] += a_[i_]*bv_.x; acc[i_][1] += a_[i_]*bv_.y;
                acc[i_][2] += a_[i_]*bv_.z; acc[i_][3] += a_[i_]*bv_.w;
            }
        }
    }
    #pragma unroll
    for (int i = 0; i < 8; i++){
        float4 v = make_float4(acc[i][0],acc[i][1],acc[i][2],acc[i][3]);
        *(float4*)&g_yp[(size_t)s*(BSZ*DIMC*MODE) + ((size_t)b*DIMC + rg*8 + i)*MODE + cg*4] = v;
    }
}

__global__ void k_reduce_y(){
    int i = blockIdx.x * 256 + threadIdx.x;   // < 262144
    float s = 0.f;
    #pragma unroll
    for (int k = 0; k < Y_SPLITS; k++) s += g_yp[(size_t)k*(BSZ*DIMC*MODE) + i];
    g_y[i] = s;
}

// ====== fused layer output: 64 x 256 tile ==================================
// h'[b,o,x] = y[b,o,:]@basesT[:,x] + conv_term + bias[o]
//   layers 1,2: conv K-range = 64 channels of hin (tiles 8..11)
//   layer 0   : conv K-range = 3 x-channels via Wc0T / g_xT   (tail3)
// non-last: hout = gelu(h'); last: out = gelu(h'^T@W1+b1)@W2+b2 (fused,
// processed in two 128-column halves so Csm fits in smem)
#define POOL_FLOATS (64*132 + 16*128)
__global__ void __launch_bounds__(256) k_L(
    const float* __restrict__ hin, float* __restrict__ hout,
    const float* __restrict__ Wconv_l, const float* __restrict__ biasv,
    const float* __restrict__ W1, const float* __restrict__ b1,
    const float* __restrict__ W2, const float* __restrict__ b2,
    float* __restrict__ out, int tail3, int is_last)
{
    __shared__ float pool[POOL_FLOATS];
    float (*As)[72]  = (float(*)[72])pool;             // 16*72  = 1152 floats
    float (*Bs)[256] = (float(*)[256])(pool + 1152);   // 16*256 = 4096 floats
    float (*Csm)[132] = (float(*)[132])pool;           // epilogue: 64*132
    float (*W1s)[128] = (float(*)[128])(pool + 64*132);// epilogue: 16*128

    int b = blockIdx.y;
    int x0 = blockIdx.x * 256;
    int tid = threadIdx.x;
    int ty = tid >> 5, tx = tid & 31;       // rows ty*8..+7, cols tx*8..+7
    float acc[8][8] = {};

    int ar = tid >> 2, aq = tid & 3;        // A staging: 64 rows x 16 k, 1 float4/thr
    int brr = tid >> 4, bcc = tid & 15;     // B staging: 16 rows, 4 float4/thr
    int nkt = tail3 ? 8 : 12;
    for (int kt = 0; kt < nkt; kt++){
        float4 av;
        if (kt < 8) av = *(const float4*)&g_y[((size_t)b*DIMC + ar)*MODE + kt*16 + aq*4];
        else        av = *(const float4*)&Wconv_l[(size_t)ar*DIMC + (kt-8)*16 + aq*4];
        int kg = kt*16 + brr;
        const float* bptr = (kt < 8) ? &g_basesT[(size_t)kg*NXS + x0]
                                     : &hin[((size_t)b*DIMC + (kg - 128))*NXS + x0];
        float4 bv[4];
        #pragma unroll
        for (int s = 0; s < 4; s++) bv[s] = *(const float4*)&bptr[(bcc + 16*s)*4];
        __syncthreads();
        As[aq*4+0][ar] = av.x; As[aq*4+1][ar] = av.y;
        As[aq*4+2][ar] = av.z; As[aq*4+3][ar] = av.w;
        #pragma unroll
        for (int s = 0; s < 4; s++) *(float4*)&Bs[brr][(bcc + 16*s)*4] = bv[s];
        __syncthreads();
        #pragma unroll
        for (int kk = 0; kk < 16; kk++){
            float a[8], bb[8];
            *(float4*)&a[0] = *(const float4*)&As[kk][ty*8];
            *(float4*)&a[4] = *(const float4*)&As[kk][ty*8+4];
            *(float4*)&bb[0] = *(const float4*)&Bs[kk][tx*8];
            *(float4*)&bb[4] = *(const float4*)&Bs[kk][tx*8+4];
            #pragma unroll
            for (int i = 0; i < 8; i++)
                #pragma unroll
                for (int j = 0; j < 8; j++)
                    acc[i][j] += a[i]*bb[j];
        }
    }
    if (tail3){
        // K tail of 3: Wc0T (3x64) x xT (3x256)
        __syncthreads();
        if (tid < 192){
            int d = tid >> 6, r = tid & 63;
            As[d][r] = g_Wc0T[d*DIMC + r];
        }
        if (tid < 192){
            int d = tid / 64, c4 = tid % 64;
            *(float4*)&Bs[d][c4*4] =
                *(const float4*)&g_xT[((size_t)b*IN_DIM + d)*NXS + x0 + c4*4];
        }
        __syncthreads();
        #pragma unroll
        for (int kk = 0; kk < 3; kk++){
            float a[8], bb[8];
            *(float4*)&a[0] = *(const float4*)&As[kk][ty*8];
            *(float4*)&a[4] = *(const float4*)&As[kk][ty*8+4];
            *(float4*)&bb[0] = *(const float4*)&Bs[kk][tx*8];
            *(float4*)&bb[4] = *(const float4*)&Bs[kk][tx*8+4];
            #pragma unroll
            for (int i = 0; i < 8; i++)
                #pragma unroll
                for (int j = 0; j < 8; j++)
                    acc[i][j] += a[i]*bb[j];
        }
    }
    const float* bvec = tail3 ? g_bias0 : biasv;

    if (!is_last){
        #pragma unroll
        for (int i = 0; i < 8; i++){
            int c = ty*8 + i;
            float bias = bvec[c];
            float4 v0, v1;
            v0.x = gelu_f(acc[i][0]+bias); v0.y = gelu_f(acc[i][1]+bias);
            v0.z = gelu_f(acc[i][2]+bias); v0.w = gelu_f(acc[i][3]+bias);
            v1.x = gelu_f(acc[i][4]+bias); v1.y = gelu_f(acc[i][5]+bias);
            v1.z = gelu_f(acc[i][6]+bias); v1.w = gelu_f(acc[i][7]+bias);
            float* dst = &hout[((size_t)b*DIMC + c)*NXS + x0 + tx*8];
            *(float4*)dst = v0; *(float4*)(dst+4) = v1;
        }
        return;
    }

    // ---- last layer: h' (no gelu) -> fused fc1(gelu) + fc2, two 128-col halves
    int xl4 = (tid & 31) * 4;           // 4 x-values per thread (within half)
    int fb  = (tid >> 5) * 16;          // 16 f per warp
    #pragma unroll 1
    for (int hh = 0; hh < 2; hh++){
        __syncthreads();                 // As/Bs (or prior half) dead
        if ((tx >> 4) == hh){            // this thread owns cols in current half
            int xloc = (tx & 15) * 8;
            #pragma unroll
            for (int i = 0; i < 8; i++){
                int c = ty*8 + i;
                float bias = bvec[c];
                *(float4*)&Csm[c][xloc]     = make_float4(acc[i][0]+bias, acc[i][1]+bias,
                                                          acc[i][2]+bias, acc[i][3]+bias);
                *(float4*)&Csm[c][xloc + 4] = make_float4(acc[i][4]+bias, acc[i][5]+bias,
                                                          acc[i][6]+bias, acc[i][7]+bias);
            }
        }
        __syncthreads();

        float zacc[4][16] = {};
        for (int c0 = 0; c0 < 64; c0 += 16){
            int kk = tid >> 4, c4 = tid & 15;
            float4 w0v = *(const float4*)&W1[(size_t)(c0 + kk)*FCD + c4*4];
            float4 w1v = *(const float4*)&W1[(size_t)(c0 + kk)*FCD + (c4+16)*4];
            __syncthreads();
            *(float4*)&W1s[kk][c4*4]      = w0v;
            *(float4*)&W1s[kk][(c4+16)*4] = w1v;
            __syncthreads();
            #pragma unroll
            for (int cc = 0; cc < 16; cc++){
                float4 a4 = *(const float4*)&Csm[c0 + cc][xl4];
                #pragma unroll
                for (int q = 0; q < 16; q++){
                    float bb = W1s[cc][fb + q];
                    zacc[0][q] += a4.x * bb;
                    zacc[1][q] += a4.y * bb;
                    zacc[2][q] += a4.z * bb;
                    zacc[3][q] += a4.w * bb;
                }
            }
        }
        float part[4] = {0.f,0.f,0.f,0.f};
        #pragma unroll
        for (int q = 0; q < 16; q++){
            float b1v = b1[fb + q];
            float w2v = W2[fb + q];
            #pragma unroll
            for (int z = 0; z < 4; z++)
                part[z] += gelu_f(zacc[z][q] + b1v) * w2v;
        }
        __syncthreads();
        float* scratch = &W1s[0][0];   // [8 warps][128]
        *(float4*)&scratch[(tid >> 5)*128 + xl4] = make_float4(part[0],part[1],part[2],part[3]);
        __syncthreads();
        if (tid < 128){
            float s = b2[0];
            #pragma unroll
            for (int w = 0; w < 8; w++) s += scratch[w*128 + tid];
            out[(size_t)b*NXS + x0 + hh*128 + tid] = s;
        }
    }
}

// ---------------------------------------------------------------------------
extern "C" void kernel_launch(void* const* d_in, const int* in_sizes, int n_in,
                              void* d_out, int out_size){
    (void)in_sizes; (void)n_in; (void)out_size;
    const float* x      = (const float*)d_in[0];
    const float* bases  = (const float*)d_in[1];
    const float* wbases = (const float*)d_in[2];
    const float* product= (const float*)d_in[3];
    const float* Do     = (const float*)d_in[4];
    const float* Di     = (const float*)d_in[5];
    const float* A      = (const float*)d_in[6];
    const float* Bm     = (const float*)d_in[7];
    const float* W_sp   = (const float*)d_in[8];
    const float* W_conv = (const float*)d_in[9];
    const float* b_conv = (const float*)d_in[10];
    const float* W0     = (const float*)d_in[11];
    const float* b0     = (const float*)d_in[12];
    const float* W1     = (const float*)d_in[13];
    const float* b1     = (const float*)d_in[14];
    const float* W2     = (const float*)d_in[15];
    const float* b2     = (const float*)d_in[16];
    float* out = (float*)d_out;

    float *hA = nullptr, *hB = nullptr;
    cudaGetSymbolAddress((void**)&hA, g_h);
    cudaGetSymbolAddress((void**)&hB, g_h2);

    k_transpose<<<dim3(NXS/32, MODE/32), dim3(32,8)>>>(bases);
    k_buildHT<<<dim3(NJ, MODE), MODE>>>(Do, Di, product, A, Bm);
    k_xT<<<(BSZ*NXS*IN_DIM)/256, 256>>>(x);
    k_prep0<<<1, DIMC>>>(W_conv, W0, b0, b_conv);

    // ---- layer 0 (h0 never materialized) ----
    k_T<<<dim3(BSZ, T_SPLITS), MODE>>>(wbases);
    k_xh0<<<BSZ, 256>>>(W0, b0);
    k_xh1<<<dim3(BSZ, NJ), 256>>>();
    k_WrT<<<(NJ*DIMC*DIMC)/256, 256>>>(W_sp, 0);
    k_y_part<<<dim3(BSZ, Y_SPLITS), 256>>>();
    k_reduce_y<<<(BSZ*DIMC*MODE)/256, 256>>>();
    k_L<<<dim3(NXS/256, BSZ), 256>>>(hA /*unused*/, hA, nullptr, nullptr,
                                     W1, b1, W2, b2, out, /*tail3=*/1, /*is_last=*/0);

    // ---- layers 1,2 ----
    const float* hin = hA;
    float* hout = hB;
    for (int li = 1; li < N_LAYERS; li++){
        k_xh_part<<<dim3((BSZ*DIMC)/128, XH_SPLITS), 256>>>(hin, wbases);
        k_reduce_xh<<<(BSZ*DIMC*MODE)/256, 256>>>();
        k_xh1<<<dim3(BSZ, NJ), 256>>>();
        k_WrT<<<(NJ*DIMC*DIMC)/256, 256>>>(W_sp, li);
        k_y_part<<<dim3(BSZ, Y_SPLITS), 256>>>();
        k_reduce_y<<<(BSZ*DIMC*MODE)/256, 256>>>();
        k_L<<<dim3(NXS/256, BSZ), 256>>>(hin, hout,
                                         &W_conv[(size_t)li*DIMC*DIMC],
                                         &b_conv[(size_t)li*DIMC],
                                         W1, b1, W2, b2, out,
                                         /*tail3=*/0, /*is_last=*/(li == N_LAYERS-1) ? 1 : 0);
        const float* t = hin; hin = hout; hout = (float*)t;
    }
}

// round 6
// speedup vs baseline: 1.1619x; 1.1619x over previous
#include <cuda_runtime.h>
#include <cuda_bf16.h>
#include <math.h>
#include <stdint.h>

#define BSZ 32
#define NXS 16384
#define IN_DIM 3
#define DIMC 64
#define NJ 16
#define MODE 128
#define RANKR 4
#define FCD 128
#define N_LAYERS 3
#define XH_SPLITS 8
#define Y_SPLITS 8
#define T_SPLITS 8

__device__ float g_h [(size_t)BSZ*DIMC*NXS];
__device__ float g_h2[(size_t)BSZ*DIMC*NXS];
__device__ unsigned g_basesP[(size_t)NXS*MODE];   // per-elem packed (hi<<16|lo), [x][k]
__device__ unsigned g_wbTP[(size_t)MODE*NXS];     // per-elem packed, [kmode][x]
__device__ float g_xT[BSZ*IN_DIM*NXS];
__device__ float g_HT[NJ*MODE*MODE];
__device__ float g_xh [BSZ*DIMC*MODE];
__device__ float g_xhp[XH_SPLITS*BSZ*DIMC*MODE];
__device__ float g_xh1[BSZ*DIMC*NJ*MODE];
__device__ float g_WrT[NJ*DIMC*DIMC];
__device__ float g_y  [BSZ*DIMC*MODE];
__device__ float g_yp [Y_SPLITS*BSZ*DIMC*MODE];
__device__ float g_Tp [T_SPLITS*BSZ*4*MODE];
__device__ float g_Wc0T[IN_DIM*DIMC];
__device__ float g_bias0[DIMC];

__device__ __forceinline__ float gelu_f(float v){
    return 0.5f * v * (1.0f + erff(v * 0.70710678118654752440f));
}
// pack one fp32 as (bf16_hi<<16)|bf16_lo(residual)
__device__ __forceinline__ unsigned pk_split(float x){
    __nv_bfloat16 h = __float2bfloat16(x);
    float r = x - __bfloat162float(h);
    __nv_bfloat16 l = __float2bfloat16(r);
    return ((unsigned)__bfloat16_as_ushort(h) << 16) | (unsigned)__bfloat16_as_ushort(l);
}
__device__ __forceinline__ uint4 pk4(float4 f){
    return make_uint4(pk_split(f.x), pk_split(f.y), pk_split(f.z), pk_split(f.w));
}
// 4 packed elems -> 2 u32 of adjacent-element hi-bf16 pairs (lo = element k even in low half)
__device__ __forceinline__ uint2 up_hi(uint4 u){
    return make_uint2((u.x >> 16) | (u.y & 0xFFFF0000u), (u.z >> 16) | (u.w & 0xFFFF0000u));
}
__device__ __forceinline__ uint2 up_lo(uint4 u){
    return make_uint2((u.x & 0xFFFFu) | (u.y << 16), (u.z & 0xFFFFu) | (u.w << 16));
}
#define MMA(c,a,b) asm volatile( \
    "mma.sync.aligned.m16n8k16.row.col.f32.bf16.bf16.f32 " \
    "{%0,%1,%2,%3}, {%4,%5,%6,%7}, {%8,%9}, {%0,%1,%2,%3};" \
    : "+f"((c)[0]), "+f"((c)[1]), "+f"((c)[2]), "+f"((c)[3]) \
    : "r"((a)[0]), "r"((a)[1]), "r"((a)[2]), "r"((a)[3]), "r"((b)[0]), "r"((b)[1]))

// ---------------- prep kernels ----------------
__global__ void k_xT(const float* __restrict__ x){
    int i = blockIdx.x * 256 + threadIdx.x;
    int d = i % 3, t = i / 3;
    g_xT[((size_t)(t >> 14)*IN_DIM + d)*NXS + (t & (NXS-1))] = x[i];
}
__global__ void k_basesP(const float* __restrict__ bases){
    int i = blockIdx.x * 256 + threadIdx.x;
    g_basesP[i] = pk_split(bases[i]);
}
__global__ void k_wbTP(const float* __restrict__ wb){
    __shared__ float t[32][33];
    int x0 = blockIdx.x * 32, k0 = blockIdx.y * 32;
    for (int i = threadIdx.y; i < 32; i += 8)
        t[i][threadIdx.x] = wb[(size_t)(x0 + i)*MODE + k0 + threadIdx.x];
    __syncthreads();
    for (int i = threadIdx.y; i < 32; i += 8)
        g_wbTP[(size_t)(k0 + i)*NXS + x0 + threadIdx.x] = pk_split(t[threadIdx.x][i]);
}
__global__ void k_buildHT(const float* __restrict__ Do, const float* __restrict__ Di,
                          const float* __restrict__ pr, const float* __restrict__ A,
                          const float* __restrict__ Bm){
    int j = blockIdx.x, l = blockIdx.y, k = threadIdx.x;
    float s = Do[j*MODE + k] * Di[j*MODE + l] * pr[k*MODE + l];
    #pragma unroll
    for (int r = 0; r < RANKR; r++)
        s += A[(j*RANKR + r)*MODE + k] * Bm[(j*RANKR + r)*MODE + l];
    g_HT[((size_t)j*MODE + l)*MODE + k] = s;
}
__global__ void k_prep0(const float* __restrict__ W_conv, const float* __restrict__ W0,
                        const float* __restrict__ b0, const float* __restrict__ b_conv){
    int o = threadIdx.x;
    float w0s = 0.f, w1s = 0.f, w2s = 0.f, bb = b_conv[o];
    for (int c = 0; c < DIMC; c++){
        float wc = W_conv[o*DIMC + c];
        w0s += wc*W0[c]; w1s += wc*W0[DIMC+c]; w2s += wc*W0[2*DIMC+c];
        bb  += wc*b0[c];
    }
    g_Wc0T[o] = w0s; g_Wc0T[64+o] = w1s; g_Wc0T[128+o] = w2s; g_bias0[o] = bb;
}
__global__ void k_T(const float* __restrict__ wbases){
    int b = blockIdx.x, s = blockIdx.y;
    int x0 = s * (NXS / T_SPLITS);
    int k = threadIdx.x;
    __shared__ float xs[3][128];
    float a0=0.f, a1=0.f, a2=0.f, a3=0.f;
    for (int xt = 0; xt < (NXS/T_SPLITS)/128; xt++){
        __syncthreads();
        xs[0][k] = g_xT[((size_t)b*IN_DIM + 0)*NXS + x0 + xt*128 + k];
        xs[1][k] = g_xT[((size_t)b*IN_DIM + 1)*NXS + x0 + xt*128 + k];
        xs[2][k] = g_xT[((size_t)b*IN_DIM + 2)*NXS + x0 + xt*128 + k];
        __syncthreads();
        #pragma unroll 8
        for (int xi = 0; xi < 128; xi++){
            float w = wbases[(size_t)(x0 + xt*128 + xi)*MODE + k];
            a0 += xs[0][xi]*w; a1 += xs[1][xi]*w; a2 += xs[2][xi]*w; a3 += w;
        }
    }
    size_t base = (((size_t)s*BSZ + b)*4)*MODE + k;
    g_Tp[base] = a0; g_Tp[base+MODE] = a1; g_Tp[base+2*MODE] = a2; g_Tp[base+3*MODE] = a3;
}
__global__ void k_xh0(const float* __restrict__ W0, const float* __restrict__ b0){
    int b = blockIdx.x;
    __shared__ float Ts[4][128];
    int tid = threadIdx.x;
    for (int e = tid; e < 4*MODE; e += 256){
        int d = e >> 7, k = e & 127;
        float s = 0.f;
        #pragma unroll
        for (int s8 = 0; s8 < T_SPLITS; s8++)
            s += g_Tp[(((size_t)s8*BSZ + b)*4 + d)*MODE + k];
        Ts[d][k] = s;
    }
    __syncthreads();
    for (int o = tid; o < DIMC*MODE; o += 256){
        int c = o >> 7, k = o & 127;
        g_xh[((size_t)b*DIMC + c)*MODE + k] =
            W0[c]*Ts[0][k] + W0[DIMC+c]*Ts[1][k] + W0[2*DIMC+c]*Ts[2][k] + b0[c]*Ts[3][k];
    }
}

// ============ GEMM1 (mma.sync): xh[m,kmode] = sum_x h[m,x] wb[x,kmode] ============
__global__ void __launch_bounds__(256) k_xh_mma(const float* __restrict__ hin){
    __shared__ unsigned As[128][20];   // 16 u32 (hi 0..7 | lo 8..15) + pad
    __shared__ unsigned Bs[128][20];
    int tid = threadIdx.x, lane = tid & 31, wid = tid >> 5;
    int wm = wid >> 2, wn = wid & 3;           // 2(m) x 4(n) warps
    int g = lane >> 2, t = lane & 3;
    int m0 = blockIdx.x * 128;
    int k0 = blockIdx.y * (NXS / XH_SPLITS);
    int r = tid >> 1, h0 = (tid & 1) * 4;
    float c[4][4][4] = {};
    for (int it = 0; it < (NXS/XH_SPLITS)/16; it++){
        size_t col = (size_t)k0 + it*16 + (tid & 1)*8;
        float4 a0 = *(const float4*)&hin[(size_t)(m0 + r)*NXS + col];
        float4 a1 = *(const float4*)&hin[(size_t)(m0 + r)*NXS + col + 4];
        uint4 b0 = *(const uint4*)&g_wbTP[(size_t)r*NXS + col];
        uint4 b1 = *(const uint4*)&g_wbTP[(size_t)r*NXS + col + 4];
        uint4 p0 = pk4(a0), p1 = pk4(a1);
        __syncthreads();
        *(uint2*)&As[r][h0]    = up_hi(p0); *(uint2*)&As[r][h0+2]  = up_hi(p1);
        *(uint2*)&As[r][h0+8]  = up_lo(p0); *(uint2*)&As[r][h0+10] = up_lo(p1);
        *(uint2*)&Bs[r][h0]    = up_hi(b0); *(uint2*)&Bs[r][h0+2]  = up_hi(b1);
        *(uint2*)&Bs[r][h0+8]  = up_lo(b0); *(uint2*)&Bs[r][h0+10] = up_lo(b1);
        __syncthreads();
        unsigned Ah[4][4], Al[4][4], Bh[4][2], Bl[4][2];
        #pragma unroll
        for (int tm = 0; tm < 4; tm++){
            int am = wm*64 + tm*16 + g;
            Ah[tm][0]=As[am][t];    Ah[tm][1]=As[am+8][t];
            Ah[tm][2]=As[am][t+4];  Ah[tm][3]=As[am+8][t+4];
            Al[tm][0]=As[am][t+8];  Al[tm][1]=As[am+8][t+8];
            Al[tm][2]=As[am][t+12]; Al[tm][3]=As[am+8][t+12];
        }
        #pragma unroll
        for (int tn = 0; tn < 4; tn++){
            int bn = wn*32 + tn*8 + g;
            Bh[tn][0]=Bs[bn][t];   Bh[tn][1]=Bs[bn][t+4];
            Bl[tn][0]=Bs[bn][t+8]; Bl[tn][1]=Bs[bn][t+12];
        }
        #pragma unroll
        for (int tm = 0; tm < 4; tm++)
            #pragma unroll
            for (int tn = 0; tn < 4; tn++){
                MMA(c[tm][tn], Ah[tm], Bh[tn]);
                MMA(c[tm][tn], Al[tm], Bh[tn]);
                MMA(c[tm][tn], Ah[tm], Bl[tn]);
            }
    }
    float* dst = &g_xhp[(size_t)blockIdx.y*(BSZ*DIMC*MODE)];
    #pragma unroll
    for (int tm = 0; tm < 4; tm++)
        #pragma unroll
        for (int tn = 0; tn < 4; tn++){
            int m = m0 + wm*64 + tm*16 + g;
            int n = wn*32 + tn*8 + t*2;
            *(float2*)&dst[(size_t)m*MODE + n]     = make_float2(c[tm][tn][0], c[tm][tn][1]);
            *(float2*)&dst[(size_t)(m+8)*MODE + n] = make_float2(c[tm][tn][2], c[tm][tn][3]);
        }
}
__global__ void k_reduce_xh(){
    int i = blockIdx.x * 256 + threadIdx.x;
    float s = 0.f;
    #pragma unroll
    for (int k = 0; k < XH_SPLITS; k++) s += g_xhp[(size_t)k*(BSZ*DIMC*MODE) + i];
    g_xh[i] = s;
}

// ================= mid pipeline (fp32, known-good from R3) =================
__global__ void __launch_bounds__(256) k_xh1(){
    int b = blockIdx.x, j = blockIdx.y;
    __shared__ float xs[64][128];
    __shared__ float Bs[16][128];
    int tid = threadIdx.x, rg = tid >> 5, cg = tid & 31;
    {
        const float4* src = (const float4*)&g_xh[(size_t)b*DIMC*MODE];
        float4* dst = (float4*)&xs[0][0];
        for (int i = tid; i < 64*128/4; i += 256) dst[i] = src[i];
    }
    float acc[8][4] = {};
    for (int kt = 0; kt < 8; kt++){
        int kkB = tid >> 4, n8 = (tid & 15) * 8;
        const float* bsrc = &g_HT[((size_t)j*MODE + kt*16 + kkB)*MODE + n8];
        float4 bv0 = *(const float4*)bsrc, bv1 = *(const float4*)(bsrc + 4);
        __syncthreads();
        *(float4*)&Bs[kkB][n8] = bv0; *(float4*)&Bs[kkB][n8+4] = bv1;
        __syncthreads();
        #pragma unroll
        for (int kk = 0; kk < 16; kk++){
            int l = kt*16 + kk;
            float a_[8];
            #pragma unroll
            for (int i_ = 0; i_ < 8; i_++) a_[i_] = xs[rg*8 + i_][l];
            float4 bv_ = *(const float4*)&Bs[kk][cg*4];
            #pragma unroll
            for (int i_ = 0; i_ < 8; i_++){
                acc[i_][0] += a_[i_]*bv_.x; acc[i_][1] += a_[i_]*bv_.y;
                acc[i_][2] += a_[i_]*bv_.z; acc[i_][3] += a_[i_]*bv_.w;
            }
        }
    }
    #pragma unroll
    for (int i = 0; i < 8; i++)
        *(float4*)&g_xh1[((size_t)b*(DIMC*NJ) + (size_t)(rg*8 + i)*NJ + j)*MODE + cg*4] =
            make_float4(acc[i][0], acc[i][1], acc[i][2], acc[i][3]);
}
__global__ void k_WrT(const float* __restrict__ W_sp, int li){
    int idx = blockIdx.x * 256 + threadIdx.x;
    int o = idx & 63, p = idx >> 6;
    g_WrT[(size_t)p*DIMC + o] = W_sp[(((size_t)li*DIMC + (p >> 4))*DIMC + o)*NJ + (p & 15)];
}
__global__ void __launch_bounds__(256) k_y_part(){
    int b = blockIdx.x, s = blockIdx.y;
    int p0 = s * 128;
    __shared__ float As[16][65];
    __shared__ float Bs[16][128];
    int tid = threadIdx.x, rg = tid >> 5, cg = tid & 31;
    float acc[8][4] = {};
    for (int kt = 0; kt < 8; kt++){
        int kkA = tid >> 4, o4 = (tid & 15) * 4;
        float4 av = *(const float4*)&g_WrT[(size_t)(p0 + kt*16 + kkA)*DIMC + o4];
        int kkB = tid >> 4, n8 = (tid & 15) * 8;
        const float* bsrc = &g_xh1[((size_t)b*(DIMC*NJ) + p0 + kt*16 + kkB)*MODE + n8];
        float4 bv0 = *(const float4*)bsrc, bv1 = *(const float4*)(bsrc + 4);
        __syncthreads();
        As[kkA][o4]=av.x; As[kkA][o4+1]=av.y; As[kkA][o4+2]=av.z; As[kkA][o4+3]=av.w;
        *(float4*)&Bs[kkB][n8] = bv0; *(float4*)&Bs[kkB][n8+4] = bv1;
        __syncthreads();
        #pragma unroll
        for (int kk = 0; kk < 16; kk++){
            float a_[8];
            #pragma unroll
            for (int i_ = 0; i_ < 8; i_++) a_[i_] = As[kk][rg*8 + i_];
            float4 bv_ = *(const float4*)&Bs[kk][cg*4];
            #pragma unroll
            for (int i_ = 0; i_ < 8; i_++){
                acc[i_][0] += a_[i_]*bv_.x; acc[i_][1] += a_[i_]*bv_.y;
                acc[i_][2] += a_[i_]*bv_.z; acc[i_][3] += a_[i_]*bv_.w;
            }
        }
    }
    #pragma unroll
    for (int i = 0; i < 8; i++)
        *(float4*)&g_yp[(size_t)s*(BSZ*DIMC*MODE) + ((size_t)b*DIMC + rg*8 + i)*MODE + cg*4] =
            make_float4(acc[i][0], acc[i][1], acc[i][2], acc[i][3]);
}
__global__ void k_reduce_y(){
    int i = blockIdx.x * 256 + threadIdx.x;
    float s = 0.f;
    #pragma unroll
    for (int k = 0; k < Y_SPLITS; k++) s += g_yp[(size_t)k*(BSZ*DIMC*MODE) + i];
    g_y[i] = s;
}

// ============ GEMM2 (mma.sync): D1[x,o] = [bases|h^T] . [y|Wconv]^T ============
// block = 128 x-rows, 64 o-cols. last layer: + R3 FFMA fc1/fc2 epilogue.
#define CSW 132
__global__ void __launch_bounds__(256) k_L_mma(
    const float* __restrict__ hin, float* __restrict__ hout,
    const float* __restrict__ Wconv_l, const float* __restrict__ biasv,
    const float* __restrict__ W1, const float* __restrict__ b1,
    const float* __restrict__ W2, const float* __restrict__ b2,
    float* __restrict__ out, int tail3, int is_last)
{
    __shared__ __align__(16) float pool[64*CSW + 16*128];
    unsigned (*As)[20] = (unsigned(*)[20])pool;                  // 128x20 u32
    unsigned (*Bs)[20] = (unsigned(*)[20])(pool + 128*20);       // 64x20 u32
    float (*Csm)[CSW]  = (float(*)[CSW])pool;                    // 64 x 132
    float (*W1s)[128]  = (float(*)[128])(pool + 64*CSW);

    int tid = threadIdx.x, lane = tid & 31, wid = tid >> 5;
    int wm = wid >> 2, wn = wid & 3;           // 2(m=x) x 4(n=o) warps, warp tile 64x16
    int g = lane >> 2, t = lane & 3;
    int b = blockIdx.y;
    int x0 = blockIdx.x * 128;
    int r = tid >> 1, h0 = (tid & 1) * 4;
    int r2 = tid >> 2, q = tid & 3;
    int nch = tail3 ? 8 : 12;
    float c[4][2][4] = {};
    for (int ch = 0; ch < nch; ch++){
        uint4 p0, p1;
        if (ch < 8){
            p0 = *(const uint4*)&g_basesP[(size_t)(x0 + r)*MODE + ch*16 + (tid & 1)*8];
            p1 = *(const uint4*)&g_basesP[(size_t)(x0 + r)*MODE + ch*16 + (tid & 1)*8 + 4];
        } else {
            int cb = (ch - 8)*16 + (tid & 1)*8;
            float4 f0, f1;
            f0.x = hin[((size_t)b*DIMC + cb+0)*NXS + x0 + r];
            f0.y = hin[((size_t)b*DIMC + cb+1)*NXS + x0 + r];
            f0.z = hin[((size_t)b*DIMC + cb+2)*NXS + x0 + r];
            f0.w = hin[((size_t)b*DIMC + cb+3)*NXS + x0 + r];
            f1.x = hin[((size_t)b*DIMC + cb+4)*NXS + x0 + r];
            f1.y = hin[((size_t)b*DIMC + cb+5)*NXS + x0 + r];
            f1.z = hin[((size_t)b*DIMC + cb+6)*NXS + x0 + r];
            f1.w = hin[((size_t)b*DIMC + cb+7)*NXS + x0 + r];
            p0 = pk4(f0); p1 = pk4(f1);
        }
        float4 fb = (ch < 8)
            ? *(const float4*)&g_y[((size_t)b*DIMC + r2)*MODE + ch*16 + q*4]
            : *(const float4*)&Wconv_l[(size_t)r2*DIMC + (ch-8)*16 + q*4];
        uint4 pb = pk4(fb);
        __syncthreads();
        *(uint2*)&As[r][h0]    = up_hi(p0); *(uint2*)&As[r][h0+2]  = up_hi(p1);
        *(uint2*)&As[r][h0+8]  = up_lo(p0); *(uint2*)&As[r][h0+10] = up_lo(p1);
        *(uint2*)&Bs[r2][q*2]   = up_hi(pb);
        *(uint2*)&Bs[r2][q*2+8] = up_lo(pb);
        __syncthreads();
        unsigned Ah[4][4], Al[4][4], Bh[2][2], Bl[2][2];
        #pragma unroll
        for (int tm = 0; tm < 4; tm++){
            int am = wm*64 + tm*16 + g;
            Ah[tm][0]=As[am][t];    Ah[tm][1]=As[am+8][t];
            Ah[tm][2]=As[am][t+4];  Ah[tm][3]=As[am+8][t+4];
            Al[tm][0]=As[am][t+8];  Al[tm][1]=As[am+8][t+8];
            Al[tm][2]=As[am][t+12]; Al[tm][3]=As[am+8][t+12];
        }
        #pragma unroll
        for (int tn = 0; tn < 2; tn++){
            int bn = wn*16 + tn*8 + g;
            Bh[tn][0]=Bs[bn][t];   Bh[tn][1]=Bs[bn][t+4];
            Bl[tn][0]=Bs[bn][t+8]; Bl[tn][1]=Bs[bn][t+12];
        }
        #pragma unroll
        for (int tm = 0; tm < 4; tm++)
            #pragma unroll
            for (int tn = 0; tn < 2; tn++){
                MMA(c[tm][tn], Ah[tm], Bh[tn]);
                MMA(c[tm][tn], Al[tm], Bh[tn]);
                MMA(c[tm][tn], Ah[tm], Bl[tn]);
            }
    }
    __syncthreads();                  // As/Bs done; pool becomes Csm
    #pragma unroll
    for (int tm = 0; tm < 4; tm++)
        #pragma unroll
        for (int tn = 0; tn < 2; tn++){
            int xr = wm*64 + tm*16 + g;
            int oc = wn*16 + tn*8 + t*2;
            Csm[oc][xr]     = c[tm][tn][0]; Csm[oc+1][xr]   = c[tm][tn][1];
            Csm[oc][xr+8]   = c[tm][tn][2]; Csm[oc+1][xr+8] = c[tm][tn][3];
        }
    __syncthreads();

    // bias (+ layer-0 K=3 tail) and either gelu->hout or keep for MLP
    {
        int o = tid >> 2;
        float bias = tail3 ? g_bias0[o] : biasv[o];
        float w0 = 0.f, w1 = 0.f, w2c = 0.f;
        if (tail3){ w0 = g_Wc0T[o]; w1 = g_Wc0T[64+o]; w2c = g_Wc0T[128+o]; }
        #pragma unroll 4
        for (int j = 0; j < 32; j++){
            int xr = (tid & 3)*32 + j;
            float v = Csm[o][xr] + bias;
            if (tail3){
                int gx = x0 + xr;
                v += g_xT[((size_t)b*IN_DIM + 0)*NXS + gx]*w0
                   + g_xT[((size_t)b*IN_DIM + 1)*NXS + gx]*w1
                   + g_xT[((size_t)b*IN_DIM + 2)*NXS + gx]*w2c;
            }
            if (!is_last) hout[((size_t)b*DIMC + o)*NXS + x0 + xr] = gelu_f(v);
            else          Csm[o][xr] = v;
        }
    }
    if (!is_last) return;

    // ---- last layer: fused fc1(gelu)+fc2 (R3 known-good FFMA epilogue) ----
    __syncthreads();
    int xl4 = (tid & 31) * 4;
    int fbq = (tid >> 5) * 16;
    float zacc[4][16] = {};
    for (int c0 = 0; c0 < 64; c0 += 16){
        int kk = tid >> 4, c4 = tid & 15;
        float4 w0v = *(const float4*)&W1[(size_t)(c0 + kk)*FCD + c4*4];
        float4 w1v = *(const float4*)&W1[(size_t)(c0 + kk)*FCD + (c4+16)*4];
        __syncthreads();
        *(float4*)&W1s[kk][c4*4]      = w0v;
        *(float4*)&W1s[kk][(c4+16)*4] = w1v;
        __syncthreads();
        #pragma unroll
        for (int cc = 0; cc < 16; cc++){
            float4 a4 = *(const float4*)&Csm[c0 + cc][xl4];
            #pragma unroll
            for (int qq = 0; qq < 16; qq++){
                float bb = W1s[cc][fbq + qq];
                zacc[0][qq] += a4.x * bb;
                zacc[1][qq] += a4.y * bb;
                zacc[2][qq] += a4.z * bb;
                zacc[3][qq] += a4.w * bb;
            }
        }
    }
    float part[4] = {0.f,0.f,0.f,0.f};
    #pragma unroll
    for (int qq = 0; qq < 16; qq++){
        float b1v = b1[fbq + qq];
        float w2v = W2[fbq + qq];
        #pragma unroll
        for (int z = 0; z < 4; z++)
            part[z] += gelu_f(zacc[z][qq] + b1v) * w2v;
    }
    __syncthreads();
    float* scratch = &W1s[0][0];
    *(float4*)&scratch[(tid >> 5)*128 + xl4] = make_float4(part[0],part[1],part[2],part[3]);
    __syncthreads();
    if (tid < 128){
        float s = b2[0];
        #pragma unroll
        for (int w = 0; w < 8; w++) s += scratch[w*128 + tid];
        out[(size_t)b*NXS + x0 + tid] = s;
    }
}

// ---------------------------------------------------------------------------
extern "C" void kernel_launch(void* const* d_in, const int* in_sizes, int n_in,
                              void* d_out, int out_size){
    (void)in_sizes; (void)n_in; (void)out_size;
    const float* x      = (const float*)d_in[0];
    const float* bases  = (const float*)d_in[1];
    const float* wbases = (const float*)d_in[2];
    const float* product= (const float*)d_in[3];
    const float* Do     = (const float*)d_in[4];
    const float* Di     = (const float*)d_in[5];
    const float* A      = (const float*)d_in[6];
    const float* Bm     = (const float*)d_in[7];
    const float* W_sp   = (const float*)d_in[8];
    const float* W_conv = (const float*)d_in[9];
    const float* b_conv = (const float*)d_in[10];
    const float* W0     = (const float*)d_in[11];
    const float* b0     = (const float*)d_in[12];
    const float* W1     = (const float*)d_in[13];
    const float* b1     = (const float*)d_in[14];
    const float* W2     = (const float*)d_in[15];
    const float* b2     = (const float*)d_in[16];
    float* out = (float*)d_out;

    float *hA = nullptr, *hB = nullptr;
    cudaGetSymbolAddress((void**)&hA, g_h);
    cudaGetSymbolAddress((void**)&hB, g_h2);

    k_basesP<<<(NXS*MODE)/256, 256>>>(bases);
    k_wbTP<<<dim3(NXS/32, MODE/32), dim3(32,8)>>>(wbases);
    k_buildHT<<<dim3(NJ, MODE), MODE>>>(Do, Di, product, A, Bm);
    k_xT<<<(BSZ*NXS*IN_DIM)/256, 256>>>(x);
    k_prep0<<<1, DIMC>>>(W_conv, W0, b0, b_conv);

    // ---- layer 0 (h0 never materialized) ----
    k_T<<<dim3(BSZ, T_SPLITS), MODE>>>(wbases);
    k_xh0<<<BSZ, 256>>>(W0, b0);
    k_xh1<<<dim3(BSZ, NJ), 256>>>();
    k_WrT<<<(NJ*DIMC*DIMC)/256, 256>>>(W_sp, 0);
    k_y_part<<<dim3(BSZ, Y_SPLITS), 256>>>();
    k_reduce_y<<<(BSZ*DIMC*MODE)/256, 256>>>();
    k_L_mma<<<dim3(NXS/128, BSZ), 256>>>(hA, hA, nullptr, nullptr,
                                         W1, b1, W2, b2, out, 1, 0);
    // ---- layers 1,2 ----
    const float* hin = hA;
    float* hout = hB;
    for (int li = 1; li < N_LAYERS; li++){
        k_xh_mma<<<dim3((BSZ*DIMC)/128, XH_SPLITS), 256>>>(hin);
        k_reduce_xh<<<(BSZ*DIMC*MODE)/256, 256>>>();
        k_xh1<<<dim3(BSZ, NJ), 256>>>();
        k_WrT<<<(NJ*DIMC*DIMC)/256, 256>>>(W_sp, li);
        k_y_part<<<dim3(BSZ, Y_SPLITS), 256>>>();
        k_reduce_y<<<(BSZ*DIMC*MODE)/256, 256>>>();
        k_L_mma<<<dim3(NXS/128, BSZ), 256>>>(hin, hout,
                                             &W_conv[(size_t)li*DIMC*DIMC],
                                             &b_conv[(size_t)li*DIMC],
                                             W1, b1, W2, b2, out,
                                             0, (li == N_LAYERS-1) ? 1 : 0);
        const float* t = hin; hin = hout; hout = (float*)t;
    }
}

// round 7
// speedup vs baseline: 1.3802x; 1.1879x over previous
#include <cuda_runtime.h>
#include <cuda_bf16.h>
#include <math.h>
#include <stdint.h>

#define BSZ 32
#define NXS 16384
#define IN_DIM 3
#define DIMC 64
#define NJ 16
#define MODE 128
#define RANKR 4
#define FCD 128
#define N_LAYERS 3
#define XH_SPLITS 8
#define Y_SPLITS 8
#define T_SPLITS 8

__device__ unsigned g_hcA[(size_t)BSZ*DIMC*NXS];  // packed h, c-major [b*64+c][x]
__device__ unsigned g_hcB[(size_t)BSZ*DIMC*NXS];
__device__ unsigned g_hxA[(size_t)BSZ*NXS*DIMC];  // packed h, x-major [b][x][c]
__device__ unsigned g_hxB[(size_t)BSZ*NXS*DIMC];
__device__ unsigned g_basesP[(size_t)NXS*MODE];   // packed (hi<<16|lo), [x][k]
__device__ unsigned g_wbTP[(size_t)MODE*NXS];     // packed, [kmode][x]
__device__ float g_xT[BSZ*IN_DIM*NXS];
__device__ float g_HT[NJ*MODE*MODE];
__device__ float g_xh [BSZ*DIMC*MODE];
__device__ float g_xhp[XH_SPLITS*BSZ*DIMC*MODE];
__device__ float g_xh1[BSZ*DIMC*NJ*MODE];
__device__ float g_WrT[NJ*DIMC*DIMC];
__device__ float g_y  [BSZ*DIMC*MODE];
__device__ float g_yp [Y_SPLITS*BSZ*DIMC*MODE];
__device__ float g_Tp [T_SPLITS*BSZ*4*MODE];
__device__ float g_Wc0T[IN_DIM*DIMC];
__device__ float g_bias0[DIMC];

__device__ __forceinline__ float gelu_f(float v){
    return 0.5f * v * (1.0f + erff(v * 0.70710678118654752440f));
}
__device__ __forceinline__ unsigned pk_split(float x){
    __nv_bfloat16 h = __float2bfloat16(x);
    float r = x - __bfloat162float(h);
    __nv_bfloat16 l = __float2bfloat16(r);
    return ((unsigned)__bfloat16_as_ushort(h) << 16) | (unsigned)__bfloat16_as_ushort(l);
}
__device__ __forceinline__ uint4 pk4(float4 f){
    return make_uint4(pk_split(f.x), pk_split(f.y), pk_split(f.z), pk_split(f.w));
}
__device__ __forceinline__ uint2 up_hi(uint4 u){
    return make_uint2((u.x >> 16) | (u.y & 0xFFFF0000u), (u.z >> 16) | (u.w & 0xFFFF0000u));
}
__device__ __forceinline__ uint2 up_lo(uint4 u){
    return make_uint2((u.x & 0xFFFFu) | (u.y << 16), (u.z & 0xFFFFu) | (u.w << 16));
}
#define MMA(c,a,b) asm volatile( \
    "mma.sync.aligned.m16n8k16.row.col.f32.bf16.bf16.f32 " \
    "{%0,%1,%2,%3}, {%4,%5,%6,%7}, {%8,%9}, {%0,%1,%2,%3};" \
    : "+f"((c)[0]), "+f"((c)[1]), "+f"((c)[2]), "+f"((c)[3]) \
    : "r"((a)[0]), "r"((a)[1]), "r"((a)[2]), "r"((a)[3]), "r"((b)[0]), "r"((b)[1]))

// ---------------- prep ----------------
__global__ void k_xT(const float* __restrict__ x){
    int i = blockIdx.x * 256 + threadIdx.x;
    int d = i % 3, t = i / 3;
    g_xT[((size_t)(t >> 14)*IN_DIM + d)*NXS + (t & (NXS-1))] = x[i];
}
__global__ void k_basesP(const float* __restrict__ bases){
    int i = blockIdx.x * 256 + threadIdx.x;
    g_basesP[i] = pk_split(bases[i]);
}
__global__ void k_wbTP(const float* __restrict__ wb){
    __shared__ float t[32][33];
    int x0 = blockIdx.x * 32, k0 = blockIdx.y * 32;
    for (int i = threadIdx.y; i < 32; i += 8)
        t[i][threadIdx.x] = wb[(size_t)(x0 + i)*MODE + k0 + threadIdx.x];
    __syncthreads();
    for (int i = threadIdx.y; i < 32; i += 8)
        g_wbTP[(size_t)(k0 + i)*NXS + x0 + threadIdx.x] = pk_split(t[threadIdx.x][i]);
}
__global__ void k_buildHT(const float* __restrict__ Do, const float* __restrict__ Di,
                          const float* __restrict__ pr, const float* __restrict__ A,
                          const float* __restrict__ Bm){
    int j = blockIdx.x, l = blockIdx.y, k = threadIdx.x;
    float s = Do[j*MODE + k] * Di[j*MODE + l] * pr[k*MODE + l];
    #pragma unroll
    for (int r = 0; r < RANKR; r++)
        s += A[(j*RANKR + r)*MODE + k] * Bm[(j*RANKR + r)*MODE + l];
    g_HT[((size_t)j*MODE + l)*MODE + k] = s;
}
__global__ void k_prep0(const float* __restrict__ W_conv, const float* __restrict__ W0,
                        const float* __restrict__ b0, const float* __restrict__ b_conv){
    int o = threadIdx.x;
    float w0s = 0.f, w1s = 0.f, w2s = 0.f, bb = b_conv[o];
    for (int c = 0; c < DIMC; c++){
        float wc = W_conv[o*DIMC + c];
        w0s += wc*W0[c]; w1s += wc*W0[DIMC+c]; w2s += wc*W0[2*DIMC+c];
        bb  += wc*b0[c];
    }
    g_Wc0T[o] = w0s; g_Wc0T[64+o] = w1s; g_Wc0T[128+o] = w2s; g_bias0[o] = bb;
}
__global__ void k_T(const float* __restrict__ wbases){
    int b = blockIdx.x, s = blockIdx.y;
    int x0 = s * (NXS / T_SPLITS);
    int k = threadIdx.x;
    __shared__ float xs[3][128];
    float a0=0.f, a1=0.f, a2=0.f, a3=0.f;
    for (int xt = 0; xt < (NXS/T_SPLITS)/128; xt++){
        __syncthreads();
        xs[0][k] = g_xT[((size_t)b*IN_DIM + 0)*NXS + x0 + xt*128 + k];
        xs[1][k] = g_xT[((size_t)b*IN_DIM + 1)*NXS + x0 + xt*128 + k];
        xs[2][k] = g_xT[((size_t)b*IN_DIM + 2)*NXS + x0 + xt*128 + k];
        __syncthreads();
        #pragma unroll 8
        for (int xi = 0; xi < 128; xi++){
            float w = wbases[(size_t)(x0 + xt*128 + xi)*MODE + k];
            a0 += xs[0][xi]*w; a1 += xs[1][xi]*w; a2 += xs[2][xi]*w; a3 += w;
        }
    }
    size_t base = (((size_t)s*BSZ + b)*4)*MODE + k;
    g_Tp[base] = a0; g_Tp[base+MODE] = a1; g_Tp[base+2*MODE] = a2; g_Tp[base+3*MODE] = a3;
}
__global__ void k_xh0(const float* __restrict__ W0, const float* __restrict__ b0){
    int b = blockIdx.x;
    __shared__ float Ts[4][128];
    int tid = threadIdx.x;
    for (int e = tid; e < 4*MODE; e += 256){
        int d = e >> 7, k = e & 127;
        float s = 0.f;
        #pragma unroll
        for (int s8 = 0; s8 < T_SPLITS; s8++)
            s += g_Tp[(((size_t)s8*BSZ + b)*4 + d)*MODE + k];
        Ts[d][k] = s;
    }
    __syncthreads();
    for (int o = tid; o < DIMC*MODE; o += 256){
        int c = o >> 7, k = o & 127;
        g_xh[((size_t)b*DIMC + c)*MODE + k] =
            W0[c]*Ts[0][k] + W0[DIMC+c]*Ts[1][k] + W0[2*DIMC+c]*Ts[2][k] + b0[c]*Ts[3][k];
    }
}

// ============ GEMM1 (mma.sync, pipelined): xh[m,n] = sum_x h[m,x] wb[x,n] ============
__global__ void __launch_bounds__(256) k_xh_mma(const unsigned* __restrict__ hcP){
    __shared__ unsigned As[2][128][20];
    __shared__ unsigned Bs[2][128][20];
    int tid = threadIdx.x, lane = tid & 31, wid = tid >> 5;
    int wm = wid >> 2, wn = wid & 3;
    int g = lane >> 2, t = lane & 3;
    int m0 = blockIdx.x * 128;
    int k0 = blockIdx.y * (NXS / XH_SPLITS);
    int r = tid >> 1, h0 = (tid & 1) * 4;
    const int NIT = (NXS/XH_SPLITS)/16;
    float c[4][4][4] = {};
    uint4 a0, a1, b0, b1;
    {
        size_t col = (size_t)k0 + (tid & 1)*8;
        a0 = *(const uint4*)&hcP[(size_t)(m0 + r)*NXS + col];
        a1 = *(const uint4*)&hcP[(size_t)(m0 + r)*NXS + col + 4];
        b0 = *(const uint4*)&g_wbTP[(size_t)r*NXS + col];
        b1 = *(const uint4*)&g_wbTP[(size_t)r*NXS + col + 4];
        *(uint2*)&As[0][r][h0]    = up_hi(a0); *(uint2*)&As[0][r][h0+2]  = up_hi(a1);
        *(uint2*)&As[0][r][h0+8]  = up_lo(a0); *(uint2*)&As[0][r][h0+10] = up_lo(a1);
        *(uint2*)&Bs[0][r][h0]    = up_hi(b0); *(uint2*)&Bs[0][r][h0+2]  = up_hi(b1);
        *(uint2*)&Bs[0][r][h0+8]  = up_lo(b0); *(uint2*)&Bs[0][r][h0+10] = up_lo(b1);
    }
    __syncthreads();
    for (int it = 0; it < NIT; it++){
        int cur = it & 1, nxt = cur ^ 1;
        if (it + 1 < NIT){
            size_t col = (size_t)k0 + (it+1)*16 + (tid & 1)*8;
            a0 = *(const uint4*)&hcP[(size_t)(m0 + r)*NXS + col];
            a1 = *(const uint4*)&hcP[(size_t)(m0 + r)*NXS + col + 4];
            b0 = *(const uint4*)&g_wbTP[(size_t)r*NXS + col];
            b1 = *(const uint4*)&g_wbTP[(size_t)r*NXS + col + 4];
        }
        unsigned Ah[4][4], Al[4][4], Bh[4][2], Bl[4][2];
        #pragma unroll
        for (int tm = 0; tm < 4; tm++){
            int am = wm*64 + tm*16 + g;
            Ah[tm][0]=As[cur][am][t];    Ah[tm][1]=As[cur][am+8][t];
            Ah[tm][2]=As[cur][am][t+4];  Ah[tm][3]=As[cur][am+8][t+4];
            Al[tm][0]=As[cur][am][t+8];  Al[tm][1]=As[cur][am+8][t+8];
            Al[tm][2]=As[cur][am][t+12]; Al[tm][3]=As[cur][am+8][t+12];
        }
        #pragma unroll
        for (int tn = 0; tn < 4; tn++){
            int bn = wn*32 + tn*8 + g;
            Bh[tn][0]=Bs[cur][bn][t];   Bh[tn][1]=Bs[cur][bn][t+4];
            Bl[tn][0]=Bs[cur][bn][t+8]; Bl[tn][1]=Bs[cur][bn][t+12];
        }
        #pragma unroll
        for (int tm = 0; tm < 4; tm++)
            #pragma unroll
            for (int tn = 0; tn < 4; tn++){
                MMA(c[tm][tn], Ah[tm], Bh[tn]);
                MMA(c[tm][tn], Al[tm], Bh[tn]);
                MMA(c[tm][tn], Ah[tm], Bl[tn]);
            }
        if (it + 1 < NIT){
            *(uint2*)&As[nxt][r][h0]    = up_hi(a0); *(uint2*)&As[nxt][r][h0+2]  = up_hi(a1);
            *(uint2*)&As[nxt][r][h0+8]  = up_lo(a0); *(uint2*)&As[nxt][r][h0+10] = up_lo(a1);
            *(uint2*)&Bs[nxt][r][h0]    = up_hi(b0); *(uint2*)&Bs[nxt][r][h0+2]  = up_hi(b1);
            *(uint2*)&Bs[nxt][r][h0+8]  = up_lo(b0); *(uint2*)&Bs[nxt][r][h0+10] = up_lo(b1);
        }
        __syncthreads();
    }
    float* dst = &g_xhp[(size_t)blockIdx.y*(BSZ*DIMC*MODE)];
    #pragma unroll
    for (int tm = 0; tm < 4; tm++)
        #pragma unroll
        for (int tn = 0; tn < 4; tn++){
            int m = m0 + wm*64 + tm*16 + g;
            int n = wn*32 + tn*8 + t*2;
            *(float2*)&dst[(size_t)m*MODE + n]     = make_float2(c[tm][tn][0], c[tm][tn][1]);
            *(float2*)&dst[(size_t)(m+8)*MODE + n] = make_float2(c[tm][tn][2], c[tm][tn][3]);
        }
}
__global__ void k_reduce_xh(){
    int i = blockIdx.x * 256 + threadIdx.x;
    float s = 0.f;
    #pragma unroll
    for (int k = 0; k < XH_SPLITS; k++) s += g_xhp[(size_t)k*(BSZ*DIMC*MODE) + i];
    g_xh[i] = s;
}

// ================= mid pipeline (fp32, known-good) =================
__global__ void __launch_bounds__(256) k_xh1(){
    int b = blockIdx.x, j = blockIdx.y;
    __shared__ float xs[64][128];
    __shared__ float Bs[16][128];
    int tid = threadIdx.x, rg = tid >> 5, cg = tid & 31;
    {
        const float4* src = (const float4*)&g_xh[(size_t)b*DIMC*MODE];
        float4* dst = (float4*)&xs[0][0];
        for (int i = tid; i < 64*128/4; i += 256) dst[i] = src[i];
    }
    float acc[8][4] = {};
    for (int kt = 0; kt < 8; kt++){
        int kkB = tid >> 4, n8 = (tid & 15) * 8;
        const float* bsrc = &g_HT[((size_t)j*MODE + kt*16 + kkB)*MODE + n8];
        float4 bv0 = *(const float4*)bsrc, bv1 = *(const float4*)(bsrc + 4);
        __syncthreads();
        *(float4*)&Bs[kkB][n8] = bv0; *(float4*)&Bs[kkB][n8+4] = bv1;
        __syncthreads();
        #pragma unroll
        for (int kk = 0; kk < 16; kk++){
            int l = kt*16 + kk;
            float a_[8];
            #pragma unroll
            for (int i_ = 0; i_ < 8; i_++) a_[i_] = xs[rg*8 + i_][l];
            float4 bv_ = *(const float4*)&Bs[kk][cg*4];
            #pragma unroll
            for (int i_ = 0; i_ < 8; i_++){
                acc[i_][0] += a_[i_]*bv_.x; acc[i_][1] += a_[i_]*bv_.y;
                acc[i_][2] += a_[i_]*bv_.z; acc[i_][3] += a_[i_]*bv_.w;
            }
        }
    }
    #pragma unroll
    for (int i = 0; i < 8; i++)
        *(float4*)&g_xh1[((size_t)b*(DIMC*NJ) + (size_t)(rg*8 + i)*NJ + j)*MODE + cg*4] =
            make_float4(acc[i][0], acc[i][1], acc[i][2], acc[i][3]);
}
__global__ void k_WrT(const float* __restrict__ W_sp, int li){
    int idx = blockIdx.x * 256 + threadIdx.x;
    int o = idx & 63, p = idx >> 6;
    g_WrT[(size_t)p*DIMC + o] = W_sp[(((size_t)li*DIMC + (p >> 4))*DIMC + o)*NJ + (p & 15)];
}
__global__ void __launch_bounds__(256) k_y_part(){
    int b = blockIdx.x, s = blockIdx.y;
    int p0 = s * 128;
    __shared__ float As[16][65];
    __shared__ float Bs[16][128];
    int tid = threadIdx.x, rg = tid >> 5, cg = tid & 31;
    float acc[8][4] = {};
    for (int kt = 0; kt < 8; kt++){
        int kkA = tid >> 4, o4 = (tid & 15) * 4;
        float4 av = *(const float4*)&g_WrT[(size_t)(p0 + kt*16 + kkA)*DIMC + o4];
        int n8 = (tid & 15) * 8;
        const float* bsrc = &g_xh1[((size_t)b*(DIMC*NJ) + p0 + kt*16 + kkA)*MODE + n8];
        float4 bv0 = *(const float4*)bsrc, bv1 = *(const float4*)(bsrc + 4);
        __syncthreads();
        As[kkA][o4]=av.x; As[kkA][o4+1]=av.y; As[kkA][o4+2]=av.z; As[kkA][o4+3]=av.w;
        *(float4*)&Bs[kkA][n8] = bv0; *(float4*)&Bs[kkA][n8+4] = bv1;
        __syncthreads();
        #pragma unroll
        for (int kk = 0; kk < 16; kk++){
            float a_[8];
            #pragma unroll
            for (int i_ = 0; i_ < 8; i_++) a_[i_] = As[kk][rg*8 + i_];
            float4 bv_ = *(const float4*)&Bs[kk][cg*4];
            #pragma unroll
            for (int i_ = 0; i_ < 8; i_++){
                acc[i_][0] += a_[i_]*bv_.x; acc[i_][1] += a_[i_]*bv_.y;
                acc[i_][2] += a_[i_]*bv_.z; acc[i_][3] += a_[i_]*bv_.w;
            }
        }
    }
    #pragma unroll
    for (int i = 0; i < 8; i++)
        *(float4*)&g_yp[(size_t)s*(BSZ*DIMC*MODE) + ((size_t)b*DIMC + rg*8 + i)*MODE + cg*4] =
            make_float4(acc[i][0], acc[i][1], acc[i][2], acc[i][3]);
}
__global__ void k_reduce_y(){
    int i = blockIdx.x * 256 + threadIdx.x;
    float s = 0.f;
    #pragma unroll
    for (int k = 0; k < Y_SPLITS; k++) s += g_yp[(size_t)k*(BSZ*DIMC*MODE) + i];
    g_y[i] = s;
}

// ============ GEMM2 (mma.sync, pipelined): D1[x,o] = [bases|h] . [y|Wconv]^T ============
#define CSW 132
#define LPOOL_BYTES (64*CSW*4 + 16*128*4)
__global__ void __launch_bounds__(256) k_L_mma(
    const unsigned* __restrict__ hxin,
    unsigned* __restrict__ hcout, unsigned* __restrict__ hxout,
    const float* __restrict__ Wconv_l, const float* __restrict__ biasv,
    const float* __restrict__ W1, const float* __restrict__ b1,
    const float* __restrict__ W2, const float* __restrict__ b2,
    float* __restrict__ out, int tail3, int is_last)
{
    __shared__ __align__(16) char pool[LPOOL_BYTES];
    unsigned (*As)[128][20] = (unsigned(*)[128][20])pool;                 // 2 bufs
    unsigned (*Bs)[64][20]  = (unsigned(*)[64][20])(pool + 2*128*20*4);
    float (*Csm)[CSW]  = (float(*)[CSW])pool;
    unsigned (*CsmU)[CSW] = (unsigned(*)[CSW])pool;
    float (*W1s)[128]  = (float(*)[128])(pool + 64*CSW*4);

    int tid = threadIdx.x, lane = tid & 31, wid = tid >> 5;
    int wm = wid >> 2, wn = wid & 3;
    int g = lane >> 2, t = lane & 3;
    int b = blockIdx.y;
    int x0 = blockIdx.x * 128;
    int r = tid >> 1, h0 = (tid & 1) * 4;
    int r2 = tid >> 2, q = tid & 3;
    int nch = tail3 ? 8 : 12;
    float c[4][2][4] = {};
    uint4 p0, p1, pb;
    // preload slab 0 (always bases / y)
    {
        p0 = *(const uint4*)&g_basesP[(size_t)(x0 + r)*MODE + (tid & 1)*8];
        p1 = *(const uint4*)&g_basesP[(size_t)(x0 + r)*MODE + (tid & 1)*8 + 4];
        pb = pk4(*(const float4*)&g_y[((size_t)b*DIMC + r2)*MODE + q*4]);
        *(uint2*)&As[0][r][h0]    = up_hi(p0); *(uint2*)&As[0][r][h0+2]  = up_hi(p1);
        *(uint2*)&As[0][r][h0+8]  = up_lo(p0); *(uint2*)&As[0][r][h0+10] = up_lo(p1);
        *(uint2*)&Bs[0][r2][q*2]   = up_hi(pb);
        *(uint2*)&Bs[0][r2][q*2+8] = up_lo(pb);
    }
    __syncthreads();
    for (int ch = 0; ch < nch; ch++){
        int cur = ch & 1, nxt = cur ^ 1;
        if (ch + 1 < nch){
            int cn = ch + 1;
            if (cn < 8){
                p0 = *(const uint4*)&g_basesP[(size_t)(x0 + r)*MODE + cn*16 + (tid & 1)*8];
                p1 = *(const uint4*)&g_basesP[(size_t)(x0 + r)*MODE + cn*16 + (tid & 1)*8 + 4];
                pb = pk4(*(const float4*)&g_y[((size_t)b*DIMC + r2)*MODE + cn*16 + q*4]);
            } else {
                int cb = (cn - 8)*16 + (tid & 1)*8;
                p0 = *(const uint4*)&hxin[((size_t)b*NXS + x0 + r)*DIMC + cb];
                p1 = *(const uint4*)&hxin[((size_t)b*NXS + x0 + r)*DIMC + cb + 4];
                pb = pk4(*(const float4*)&Wconv_l[(size_t)r2*DIMC + (cn-8)*16 + q*4]);
            }
        }
        unsigned Ah[4][4], Al[4][4], Bh[2][2], Bl[2][2];
        #pragma unroll
        for (int tm = 0; tm < 4; tm++){
            int am = wm*64 + tm*16 + g;
            Ah[tm][0]=As[cur][am][t];    Ah[tm][1]=As[cur][am+8][t];
            Ah[tm][2]=As[cur][am][t+4];  Ah[tm][3]=As[cur][am+8][t+4];
            Al[tm][0]=As[cur][am][t+8];  Al[tm][1]=As[cur][am+8][t+8];
            Al[tm][2]=As[cur][am][t+12]; Al[tm][3]=As[cur][am+8][t+12];
        }
        #pragma unroll
        for (int tn = 0; tn < 2; tn++){
            int bn = wn*16 + tn*8 + g;
            Bh[tn][0]=Bs[cur][bn][t];   Bh[tn][1]=Bs[cur][bn][t+4];
            Bl[tn][0]=Bs[cur][bn][t+8]; Bl[tn][1]=Bs[cur][bn][t+12];
        }
        #pragma unroll
        for (int tm = 0; tm < 4; tm++)
            #pragma unroll
            for (int tn = 0; tn < 2; tn++){
                MMA(c[tm][tn], Ah[tm], Bh[tn]);
                MMA(c[tm][tn], Al[tm], Bh[tn]);
                MMA(c[tm][tn], Ah[tm], Bl[tn]);
            }
        if (ch + 1 < nch){
            *(uint2*)&As[nxt][r][h0]    = up_hi(p0); *(uint2*)&As[nxt][r][h0+2]  = up_hi(p1);
            *(uint2*)&As[nxt][r][h0+8]  = up_lo(p0); *(uint2*)&As[nxt][r][h0+10] = up_lo(p1);
            *(uint2*)&Bs[nxt][r2][q*2]   = up_hi(pb);
            *(uint2*)&Bs[nxt][r2][q*2+8] = up_lo(pb);
        }
        __syncthreads();
    }
    // pool becomes Csm
    #pragma unroll
    for (int tm = 0; tm < 4; tm++)
        #pragma unroll
        for (int tn = 0; tn < 2; tn++){
            int xr = wm*64 + tm*16 + g;
            int oc = wn*16 + tn*8 + t*2;
            Csm[oc][xr]     = c[tm][tn][0]; Csm[oc+1][xr]   = c[tm][tn][1];
            Csm[oc][xr+8]   = c[tm][tn][2]; Csm[oc+1][xr+8] = c[tm][tn][3];
        }
    __syncthreads();
    {
        int o = tid >> 2;
        float bias = tail3 ? g_bias0[o] : biasv[o];
        float w0 = 0.f, w1 = 0.f, w2c = 0.f;
        if (tail3){ w0 = g_Wc0T[o]; w1 = g_Wc0T[64+o]; w2c = g_Wc0T[128+o]; }
        #pragma unroll 4
        for (int j = 0; j < 32; j++){
            int xr = (tid & 3)*32 + j;
            float v = Csm[o][xr] + bias;
            if (tail3){
                int gx = x0 + xr;
                v += g_xT[((size_t)b*IN_DIM + 0)*NXS + gx]*w0
                   + g_xT[((size_t)b*IN_DIM + 1)*NXS + gx]*w1
                   + g_xT[((size_t)b*IN_DIM + 2)*NXS + gx]*w2c;
            }
            if (!is_last) CsmU[o][xr] = pk_split(gelu_f(v));
            else          Csm[o][xr] = v;
        }
    }
    __syncthreads();
    if (!is_last){
        for (int i = tid; i < DIMC*128; i += 256){
            int cc = i >> 7, xx = i & 127;
            hcout[((size_t)b*DIMC + cc)*NXS + x0 + xx] = CsmU[cc][xx];
        }
        for (int i = tid; i < DIMC*128; i += 256){
            int xx = i >> 6, cc = i & 63;
            hxout[((size_t)b*NXS + x0 + xx)*DIMC + cc] = CsmU[cc][xx];
        }
        return;
    }
    // ---- last layer: fused fc1(gelu)+fc2 (FFMA epilogue) ----
    int xl4 = (tid & 31) * 4;
    int fbq = (tid >> 5) * 16;
    float zacc[4][16] = {};
    for (int c0 = 0; c0 < 64; c0 += 16){
        int kk = tid >> 4, c4 = tid & 15;
        float4 w0v = *(const float4*)&W1[(size_t)(c0 + kk)*FCD + c4*4];
        float4 w1v = *(const float4*)&W1[(size_t)(c0 + kk)*FCD + (c4+16)*4];
        __syncthreads();
        *(float4*)&W1s[kk][c4*4]      = w0v;
        *(float4*)&W1s[kk][(c4+16)*4] = w1v;
        __syncthreads();
        #pragma unroll
        for (int cc = 0; cc < 16; cc++){
            float4 a4 = *(const float4*)&Csm[c0 + cc][xl4];
            #pragma unroll
            for (int qq = 0; qq < 16; qq++){
                float bb = W1s[cc][fbq + qq];
                zacc[0][qq] += a4.x * bb;
                zacc[1][qq] += a4.y * bb;
                zacc[2][qq] += a4.z * bb;
                zacc[3][qq] += a4.w * bb;
            }
        }
    }
    float part[4] = {0.f,0.f,0.f,0.f};
    #pragma unroll
    for (int qq = 0; qq < 16; qq++){
        float b1v = b1[fbq + qq];
        float w2v = W2[fbq + qq];
        #pragma unroll
        for (int z = 0; z < 4; z++)
            part[z] += gelu_f(zacc[z][qq] + b1v) * w2v;
    }
    __syncthreads();
    float* scratch = &W1s[0][0];
    *(float4*)&scratch[(tid >> 5)*128 + xl4] = make_float4(part[0],part[1],part[2],part[3]);
    __syncthreads();
    if (tid < 128){
        float s = b2[0];
        #pragma unroll
        for (int w = 0; w < 8; w++) s += scratch[w*128 + tid];
        out[(size_t)b*NXS + x0 + tid] = s;
    }
}

// ---------------------------------------------------------------------------
extern "C" void kernel_launch(void* const* d_in, const int* in_sizes, int n_in,
                              void* d_out, int out_size){
    (void)in_sizes; (void)n_in; (void)out_size;
    const float* x      = (const float*)d_in[0];
    const float* bases  = (const float*)d_in[1];
    const float* wbases = (const float*)d_in[2];
    const float* product= (const float*)d_in[3];
    const float* Do     = (const float*)d_in[4];
    const float* Di     = (const float*)d_in[5];
    const float* A      = (const float*)d_in[6];
    const float* Bm     = (const float*)d_in[7];
    const float* W_sp   = (const float*)d_in[8];
    const float* W_conv = (const float*)d_in[9];
    const float* b_conv = (const float*)d_in[10];
    const float* W0     = (const float*)d_in[11];
    const float* b0     = (const float*)d_in[12];
    const float* W1     = (const float*)d_in[13];
    const float* b1     = (const float*)d_in[14];
    const float* W2     = (const float*)d_in[15];
    const float* b2     = (const float*)d_in[16];
    float* out = (float*)d_out;

    unsigned *hcA, *hcB, *hxA, *hxB;
    cudaGetSymbolAddress((void**)&hcA, g_hcA);
    cudaGetSymbolAddress((void**)&hcB, g_hcB);
    cudaGetSymbolAddress((void**)&hxA, g_hxA);
    cudaGetSymbolAddress((void**)&hxB, g_hxB);

    k_basesP<<<(NXS*MODE)/256, 256>>>(bases);
    k_wbTP<<<dim3(NXS/32, MODE/32), dim3(32,8)>>>(wbases);
    k_buildHT<<<dim3(NJ, MODE), MODE>>>(Do, Di, product, A, Bm);
    k_xT<<<(BSZ*NXS*IN_DIM)/256, 256>>>(x);
    k_prep0<<<1, DIMC>>>(W_conv, W0, b0, b_conv);

    // ---- layer 0 (h0 never materialized) ----
    k_T<<<dim3(BSZ, T_SPLITS), MODE>>>(wbases);
    k_xh0<<<BSZ, 256>>>(W0, b0);
    k_xh1<<<dim3(BSZ, NJ), 256>>>();
    k_WrT<<<(NJ*DIMC*DIMC)/256, 256>>>(W_sp, 0);
    k_y_part<<<dim3(BSZ, Y_SPLITS), 256>>>();
    k_reduce_y<<<(BSZ*DIMC*MODE)/256, 256>>>();
    k_L_mma<<<dim3(NXS/128, BSZ), 256>>>(hxA, hcA, hxA, nullptr, nullptr,
                                         W1, b1, W2, b2, out, 1, 0);
    // ---- layers 1,2 ----
    const unsigned* hc = hcA;
    const unsigned* hx = hxA;
    unsigned* hcO = hcB;
    unsigned* hxO = hxB;
    for (int li = 1; li < N_LAYERS; li++){
        k_xh_mma<<<dim3((BSZ*DIMC)/128, XH_SPLITS), 256>>>(hc);
        k_reduce_xh<<<(BSZ*DIMC*MODE)/256, 256>>>();
        k_xh1<<<dim3(BSZ, NJ), 256>>>();
        k_WrT<<<(NJ*DIMC*DIMC)/256, 256>>>(W_sp, li);
        k_y_part<<<dim3(BSZ, Y_SPLITS), 256>>>();
        k_reduce_y<<<(BSZ*DIMC*MODE)/256, 256>>>();
        k_L_mma<<<dim3(NXS/128, BSZ), 256>>>(hx, hcO, hxO,
                                             &W_conv[(size_t)li*DIMC*DIMC],
                                             &b_conv[(size_t)li*DIMC],
                                             W1, b1, W2, b2, out,
                                             0, (li == N_LAYERS-1) ? 1 : 0);
        const unsigned* tc = hc; hc = hcO; hcO = (unsigned*)tc;
        const unsigned* tx = hx; hx = hxO; hxO = (unsigned*)tx;
    }
}

// round 8
// speedup vs baseline: 1.3916x; 1.0083x over previous
#include <cuda_runtime.h>
#include <cuda_bf16.h>
#include <math.h>
#include <stdint.h>

#define BSZ 32
#define NXS 16384
#define IN_DIM 3
#define DIMC 64
#define NJ 16
#define MODE 128
#define RANKR 4
#define FCD 128
#define N_LAYERS 3
#define XH_SPLITS 8
#define Y_SPLITS 8
#define T_SPLITS 8

typedef unsigned short ushortx;

// h stored pre-split: hi/lo bf16, c-major and x-major, ping/pong
__device__ ushortx g_hcHIa[(size_t)BSZ*DIMC*NXS];
__device__ ushortx g_hcLOa[(size_t)BSZ*DIMC*NXS];
__device__ ushortx g_hcHIb[(size_t)BSZ*DIMC*NXS];
__device__ ushortx g_hcLOb[(size_t)BSZ*DIMC*NXS];
__device__ ushortx g_hxHIa[(size_t)BSZ*NXS*DIMC];
__device__ ushortx g_hxLOa[(size_t)BSZ*NXS*DIMC];
__device__ ushortx g_hxHIb[(size_t)BSZ*NXS*DIMC];
__device__ ushortx g_hxLOb[(size_t)BSZ*NXS*DIMC];
__device__ ushortx g_wbTHI[(size_t)MODE*NXS];
__device__ ushortx g_wbTLO[(size_t)MODE*NXS];
__device__ ushortx g_basesHI[(size_t)NXS*MODE];
__device__ ushortx g_basesLO[(size_t)NXS*MODE];
__device__ float g_xT[BSZ*IN_DIM*NXS];
__device__ float g_HT[NJ*MODE*MODE];
__device__ float g_xh [BSZ*DIMC*MODE];
__device__ float g_xhp[XH_SPLITS*BSZ*DIMC*MODE];
__device__ float g_xh1[BSZ*DIMC*NJ*MODE];
__device__ float g_WrT[NJ*DIMC*DIMC];
__device__ float g_y  [BSZ*DIMC*MODE];
__device__ float g_yp [Y_SPLITS*BSZ*DIMC*MODE];
__device__ float g_Tp [T_SPLITS*BSZ*4*MODE];
__device__ float g_Wc0T[IN_DIM*DIMC];
__device__ float g_bias0[DIMC];

__device__ __forceinline__ float gelu_f(float v){
    return 0.5f * v * (1.0f + erff(v * 0.70710678118654752440f));
}
__device__ __forceinline__ void split2(float x, ushortx& hi, ushortx& lo){
    __nv_bfloat16 h = __float2bfloat16(x);
    hi = __bfloat16_as_ushort(h);
    lo = __bfloat16_as_ushort(__float2bfloat16(x - __bfloat162float(h)));
}
__device__ __forceinline__ unsigned pk_split(float x){
    ushortx hi, lo; split2(x, hi, lo);
    return ((unsigned)hi << 16) | (unsigned)lo;
}
__device__ __forceinline__ uint4 pk4(float4 f){
    return make_uint4(pk_split(f.x), pk_split(f.y), pk_split(f.z), pk_split(f.w));
}
__device__ __forceinline__ uint2 up_hi(uint4 u){
    return make_uint2((u.x >> 16) | (u.y & 0xFFFF0000u), (u.z >> 16) | (u.w & 0xFFFF0000u));
}
__device__ __forceinline__ uint2 up_lo(uint4 u){
    return make_uint2((u.x & 0xFFFFu) | (u.y << 16), (u.z & 0xFFFFu) | (u.w << 16));
}
#define MMA(c,a,b) asm volatile( \
    "mma.sync.aligned.m16n8k16.row.col.f32.bf16.bf16.f32 " \
    "{%0,%1,%2,%3}, {%4,%5,%6,%7}, {%8,%9}, {%0,%1,%2,%3};" \
    : "+f"((c)[0]), "+f"((c)[1]), "+f"((c)[2]), "+f"((c)[3]) \
    : "r"((a)[0]), "r"((a)[1]), "r"((a)[2]), "r"((a)[3]), "r"((b)[0]), "r"((b)[1]))
#define LDSM4(f,addr) asm volatile( \
    "ldmatrix.sync.aligned.m8n8.x4.shared.b16 {%0,%1,%2,%3}, [%4];" \
    : "=r"((f)[0]), "=r"((f)[1]), "=r"((f)[2]), "=r"((f)[3]) : "r"(addr))
#define CPA(dst,src) asm volatile("cp.async.cg.shared.global [%0], [%1], 16;" :: "r"(dst), "l"(src))
#define CPC() asm volatile("cp.async.commit_group;" ::: "memory")
#define CPW1() asm volatile("cp.async.wait_group 1;" ::: "memory")
#define CPW0() asm volatile("cp.async.wait_group 0;" ::: "memory")

// ---------------- prep ----------------
__global__ void k_xT(const float* __restrict__ x){
    int i = blockIdx.x * 256 + threadIdx.x;
    int d = i % 3, t = i / 3;
    g_xT[((size_t)(t >> 14)*IN_DIM + d)*NXS + (t & (NXS-1))] = x[i];
}
__global__ void k_basesP(const float* __restrict__ bases){
    int i = blockIdx.x * 256 + threadIdx.x;
    split2(bases[i], g_basesHI[i], g_basesLO[i]);
}
__global__ void k_wbTP(const float* __restrict__ wb){
    __shared__ float t[32][33];
    int x0 = blockIdx.x * 32, k0 = blockIdx.y * 32;
    for (int i = threadIdx.y; i < 32; i += 8)
        t[i][threadIdx.x] = wb[(size_t)(x0 + i)*MODE + k0 + threadIdx.x];
    __syncthreads();
    for (int i = threadIdx.y; i < 32; i += 8){
        size_t o = (size_t)(k0 + i)*NXS + x0 + threadIdx.x;
        split2(t[threadIdx.x][i], g_wbTHI[o], g_wbTLO[o]);
    }
}
__global__ void k_buildHT(const float* __restrict__ Do, const float* __restrict__ Di,
                          const float* __restrict__ pr, const float* __restrict__ A,
                          const float* __restrict__ Bm){
    int j = blockIdx.x, l = blockIdx.y, k = threadIdx.x;
    float s = Do[j*MODE + k] * Di[j*MODE + l] * pr[k*MODE + l];
    #pragma unroll
    for (int r = 0; r < RANKR; r++)
        s += A[(j*RANKR + r)*MODE + k] * Bm[(j*RANKR + r)*MODE + l];
    g_HT[((size_t)j*MODE + l)*MODE + k] = s;
}
__global__ void k_prep0(const float* __restrict__ W_conv, const float* __restrict__ W0,
                        const float* __restrict__ b0, const float* __restrict__ b_conv){
    int o = threadIdx.x;
    float w0s = 0.f, w1s = 0.f, w2s = 0.f, bb = b_conv[o];
    for (int c = 0; c < DIMC; c++){
        float wc = W_conv[o*DIMC + c];
        w0s += wc*W0[c]; w1s += wc*W0[DIMC+c]; w2s += wc*W0[2*DIMC+c];
        bb  += wc*b0[c];
    }
    g_Wc0T[o] = w0s; g_Wc0T[64+o] = w1s; g_Wc0T[128+o] = w2s; g_bias0[o] = bb;
}
__global__ void k_T(const float* __restrict__ wbases){
    int b = blockIdx.x, s = blockIdx.y;
    int x0 = s * (NXS / T_SPLITS);
    int k = threadIdx.x;
    __shared__ float xs[3][128];
    float a0=0.f, a1=0.f, a2=0.f, a3=0.f;
    for (int xt = 0; xt < (NXS/T_SPLITS)/128; xt++){
        __syncthreads();
        xs[0][k] = g_xT[((size_t)b*IN_DIM + 0)*NXS + x0 + xt*128 + k];
        xs[1][k] = g_xT[((size_t)b*IN_DIM + 1)*NXS + x0 + xt*128 + k];
        xs[2][k] = g_xT[((size_t)b*IN_DIM + 2)*NXS + x0 + xt*128 + k];
        __syncthreads();
        #pragma unroll 8
        for (int xi = 0; xi < 128; xi++){
            float w = wbases[(size_t)(x0 + xt*128 + xi)*MODE + k];
            a0 += xs[0][xi]*w; a1 += xs[1][xi]*w; a2 += xs[2][xi]*w; a3 += w;
        }
    }
    size_t base = (((size_t)s*BSZ + b)*4)*MODE + k;
    g_Tp[base] = a0; g_Tp[base+MODE] = a1; g_Tp[base+2*MODE] = a2; g_Tp[base+3*MODE] = a3;
}
__global__ void k_xh0(const float* __restrict__ W0, const float* __restrict__ b0){
    int b = blockIdx.x;
    __shared__ float Ts[4][128];
    int tid = threadIdx.x;
    for (int e = tid; e < 4*MODE; e += 256){
        int d = e >> 7, k = e & 127;
        float s = 0.f;
        #pragma unroll
        for (int s8 = 0; s8 < T_SPLITS; s8++)
            s += g_Tp[(((size_t)s8*BSZ + b)*4 + d)*MODE + k];
        Ts[d][k] = s;
    }
    __syncthreads();
    for (int o = tid; o < DIMC*MODE; o += 256){
        int c = o >> 7, k = o & 127;
        g_xh[((size_t)b*DIMC + c)*MODE + k] =
            W0[c]*Ts[0][k] + W0[DIMC+c]*Ts[1][k] + W0[2*DIMC+c]*Ts[2][k] + b0[c]*Ts[3][k];
    }
}

// ===== GEMM1 (mma.sync + cp.async + ldmatrix): xh[m,n] = sum_x h[m,x] wb[x,n] =====
__global__ void __launch_bounds__(256) k_xh_mma(const ushortx* __restrict__ hcHI,
                                                const ushortx* __restrict__ hcLO){
    __shared__ __align__(16) unsigned sm[4][2][128][12];   // AHI,ALO,BHI,BLO; 48B rows
    const int NIT = (NXS/XH_SPLITS)/16;
    int tid = threadIdx.x, lane = tid & 31, wid = tid >> 5;
    int wm = wid >> 2, wn = wid & 3, g = lane >> 2, t = lane & 3;
    int m0 = blockIdx.x * 128;
    int k0 = blockIdx.y * (NXS / XH_SPLITS);
    int row = tid >> 1, ch = tid & 1;
    const ushortx* src[4];
    src[0] = hcHI    + (size_t)(m0+row)*NXS + k0 + ch*8;
    src[1] = hcLO    + (size_t)(m0+row)*NXS + k0 + ch*8;
    src[2] = g_wbTHI + (size_t)row*NXS      + k0 + ch*8;
    src[3] = g_wbTLO + (size_t)row*NXS      + k0 + ch*8;
    unsigned dstb[4], bA[4];
    #pragma unroll
    for (int a = 0; a < 4; a++){
        dstb[a] = (unsigned)__cvta_generic_to_shared(&sm[a][0][row][ch*4]);
        bA[a]   = (unsigned)__cvta_generic_to_shared(&sm[a][0][0][0]);
    }
    const unsigned BUFO = 128*12*4;
    unsigned loff = (lane & 15)*48 + (lane >> 4)*16;
    float c[4][4][4] = {};
    #pragma unroll
    for (int a = 0; a < 4; a++) CPA(dstb[a], src[a]);
    CPC();
    for (int it = 0; it < NIT; it++){
        int cur = it & 1, nxt = cur ^ 1;
        if (it + 1 < NIT){
            #pragma unroll
            for (int a = 0; a < 4; a++) CPA(dstb[a] + nxt*BUFO, src[a] + (size_t)(it+1)*16);
            CPC();
            CPW1();
        } else CPW0();
        __syncthreads();
        unsigned off = cur*BUFO + loff;
        unsigned Ah[4][4], Al[4][4], Bh[2][4], Bl[2][4];
        #pragma unroll
        for (int tm = 0; tm < 4; tm++){
            LDSM4(Ah[tm], bA[0] + off + (wm*64 + tm*16)*48);
            LDSM4(Al[tm], bA[1] + off + (wm*64 + tm*16)*48);
        }
        #pragma unroll
        for (int p = 0; p < 2; p++){
            LDSM4(Bh[p], bA[2] + off + (wn*32 + p*16)*48);
            LDSM4(Bl[p], bA[3] + off + (wn*32 + p*16)*48);
        }
        #pragma unroll
        for (int tm = 0; tm < 4; tm++)
            #pragma unroll
            for (int tn = 0; tn < 4; tn++){
                int p = tn >> 1, e = tn & 1;
                unsigned bh[2] = {Bh[p][e], Bh[p][e+2]};
                unsigned bl[2] = {Bl[p][e], Bl[p][e+2]};
                MMA(c[tm][tn], Ah[tm], bh);
                MMA(c[tm][tn], Al[tm], bh);
                MMA(c[tm][tn], Ah[tm], bl);
            }
        __syncthreads();
    }
    float* dst = &g_xhp[(size_t)blockIdx.y*(BSZ*DIMC*MODE)];
    #pragma unroll
    for (int tm = 0; tm < 4; tm++)
        #pragma unroll
        for (int tn = 0; tn < 4; tn++){
            int m = m0 + wm*64 + tm*16 + g;
            int n = wn*32 + tn*8 + t*2;
            *(float2*)&dst[(size_t)m*MODE + n]     = make_float2(c[tm][tn][0], c[tm][tn][1]);
            *(float2*)&dst[(size_t)(m+8)*MODE + n] = make_float2(c[tm][tn][2], c[tm][tn][3]);
        }
}
__global__ void k_reduce_xh(){
    int i = blockIdx.x * 256 + threadIdx.x;
    float s = 0.f;
    #pragma unroll
    for (int k = 0; k < XH_SPLITS; k++) s += g_xhp[(size_t)k*(BSZ*DIMC*MODE) + i];
    g_xh[i] = s;
}

// ================= mid pipeline (fp32, known-good) =================
__global__ void __launch_bounds__(256) k_xh1(){
    int b = blockIdx.x, j = blockIdx.y;
    __shared__ float xs[64][128];
    __shared__ float Bs[16][128];
    int tid = threadIdx.x, rg = tid >> 5, cg = tid & 31;
    {
        const float4* src = (const float4*)&g_xh[(size_t)b*DIMC*MODE];
        float4* dst = (float4*)&xs[0][0];
        for (int i = tid; i < 64*128/4; i += 256) dst[i] = src[i];
    }
    float acc[8][4] = {};
    for (int kt = 0; kt < 8; kt++){
        int kkB = tid >> 4, n8 = (tid & 15) * 8;
        const float* bsrc = &g_HT[((size_t)j*MODE + kt*16 + kkB)*MODE + n8];
        float4 bv0 = *(const float4*)bsrc, bv1 = *(const float4*)(bsrc + 4);
        __syncthreads();
        *(float4*)&Bs[kkB][n8] = bv0; *(float4*)&Bs[kkB][n8+4] = bv1;
        __syncthreads();
        #pragma unroll
        for (int kk = 0; kk < 16; kk++){
            int l = kt*16 + kk;
            float a_[8];
            #pragma unroll
            for (int i_ = 0; i_ < 8; i_++) a_[i_] = xs[rg*8 + i_][l];
            float4 bv_ = *(const float4*)&Bs[kk][cg*4];
            #pragma unroll
            for (int i_ = 0; i_ < 8; i_++){
                acc[i_][0] += a_[i_]*bv_.x; acc[i_][1] += a_[i_]*bv_.y;
                acc[i_][2] += a_[i_]*bv_.z; acc[i_][3] += a_[i_]*bv_.w;
            }
        }
    }
    #pragma unroll
    for (int i = 0; i < 8; i++)
        *(float4*)&g_xh1[((size_t)b*(DIMC*NJ) + (size_t)(rg*8 + i)*NJ + j)*MODE + cg*4] =
            make_float4(acc[i][0], acc[i][1], acc[i][2], acc[i][3]);
}
__global__ void k_WrT(const float* __restrict__ W_sp, int li){
    int idx = blockIdx.x * 256 + threadIdx.x;
    int o = idx & 63, p = idx >> 6;
    g_WrT[(size_t)p*DIMC + o] = W_sp[(((size_t)li*DIMC + (p >> 4))*DIMC + o)*NJ + (p & 15)];
}
__global__ void __launch_bounds__(256) k_y_part(){
    int b = blockIdx.x, s = blockIdx.y;
    int p0 = s * 128;
    __shared__ float As[16][65];
    __shared__ float Bs[16][128];
    int tid = threadIdx.x, rg = tid >> 5, cg = tid & 31;
    float acc[8][4] = {};
    for (int kt = 0; kt < 8; kt++){
        int kkA = tid >> 4, o4 = (tid & 15) * 4;
        float4 av = *(const float4*)&g_WrT[(size_t)(p0 + kt*16 + kkA)*DIMC + o4];
        int n8 = (tid & 15) * 8;
        const float* bsrc = &g_xh1[((size_t)b*(DIMC*NJ) + p0 + kt*16 + kkA)*MODE + n8];
        float4 bv0 = *(const float4*)bsrc, bv1 = *(const float4*)(bsrc + 4);
        __syncthreads();
        As[kkA][o4]=av.x; As[kkA][o4+1]=av.y; As[kkA][o4+2]=av.z; As[kkA][o4+3]=av.w;
        *(float4*)&Bs[kkA][n8] = bv0; *(float4*)&Bs[kkA][n8+4] = bv1;
        __syncthreads();
        #pragma unroll
        for (int kk = 0; kk < 16; kk++){
            float a_[8];
            #pragma unroll
            for (int i_ = 0; i_ < 8; i_++) a_[i_] = As[kk][rg*8 + i_];
            float4 bv_ = *(const float4*)&Bs[kk][cg*4];
            #pragma unroll
            for (int i_ = 0; i_ < 8; i_++){
                acc[i_][0] += a_[i_]*bv_.x; acc[i_][1] += a_[i_]*bv_.y;
                acc[i_][2] += a_[i_]*bv_.z; acc[i_][3] += a_[i_]*bv_.w;
            }
        }
    }
    #pragma unroll
    for (int i = 0; i < 8; i++)
        *(float4*)&g_yp[(size_t)s*(BSZ*DIMC*MODE) + ((size_t)b*DIMC + rg*8 + i)*MODE + cg*4] =
            make_float4(acc[i][0], acc[i][1], acc[i][2], acc[i][3]);
}
__global__ void k_reduce_y(){
    int i = blockIdx.x * 256 + threadIdx.x;
    float s = 0.f;
    #pragma unroll
    for (int k = 0; k < Y_SPLITS; k++) s += g_yp[(size_t)k*(BSZ*DIMC*MODE) + i];
    g_y[i] = s;
}

// ===== GEMM2: D1[x,o] = [bases|h] . [y|Wconv]^T, cp.async A, ldmatrix frags =====
#define CSW 132
#define AHI_OFF 0
#define ALO_OFF 12288
#define BHI_OFF 24576
#define BLO_OFF 30720
#define ABUF 6144
#define BBUF 3072
#define LPOOL (33792 + 8192)
__global__ void __launch_bounds__(256) k_L_mma(
    const ushortx* __restrict__ hxHI, const ushortx* __restrict__ hxLO,
    ushortx* __restrict__ hcoHI, ushortx* __restrict__ hcoLO,
    ushortx* __restrict__ hxoHI, ushortx* __restrict__ hxoLO,
    const float* __restrict__ Wconv_l, const float* __restrict__ biasv,
    const float* __restrict__ W1, const float* __restrict__ b1,
    const float* __restrict__ W2, const float* __restrict__ b2,
    float* __restrict__ out, int tail3, int is_last)
{
    __shared__ __align__(16) char pool[LPOOL];
    float (*Csm)[CSW]  = (float(*)[CSW])pool;
    unsigned (*CsmU)[CSW] = (unsigned(*)[CSW])pool;
    float (*W1s)[128]  = (float(*)[128])(pool + 33792);

    int tid = threadIdx.x, lane = tid & 31, wid = tid >> 5;
    int wm = wid >> 2, wn = wid & 3, g = lane >> 2, t = lane & 3;
    int b = blockIdx.y;
    int x0 = blockIdx.x * 128;
    int row = tid >> 1, ch = tid & 1;
    int ro = tid >> 2, q = tid & 3;
    int nch = tail3 ? 8 : 12;

    unsigned dAhi = (unsigned)__cvta_generic_to_shared(pool + AHI_OFF) + row*48 + ch*16;
    unsigned dAlo = dAhi + (ALO_OFF - AHI_OFF);
    unsigned bAhi = (unsigned)__cvta_generic_to_shared(pool + AHI_OFF);
    unsigned bAlo = bAhi + ALO_OFF;
    unsigned bBhi = bAhi + BHI_OFF;
    unsigned bBlo = bAhi + BLO_OFF;
    unsigned* Bhw = (unsigned*)(pool + BHI_OFF);
    unsigned* Blw = (unsigned*)(pool + BLO_OFF);
    unsigned loff = (lane & 15)*48 + (lane >> 4)*16;

    float c[4][2][4] = {};
    // preload slab 0: cp.async A (bases), B regs -> buf0
    CPA(dAhi, g_basesHI + (size_t)(x0+row)*MODE + ch*8);
    CPA(dAlo, g_basesLO + (size_t)(x0+row)*MODE + ch*8);
    CPC();
    {
        uint4 pb = pk4(*(const float4*)&g_y[((size_t)b*DIMC + ro)*MODE + q*4]);
        *(uint2*)&Bhw[ro*12 + q*2] = up_hi(pb);
        *(uint2*)&Blw[ro*12 + q*2] = up_lo(pb);
    }
    for (int chn = 0; chn < nch; chn++){
        int cur = chn & 1, nxt = cur ^ 1;
        uint4 pbn;
        if (chn + 1 < nch){
            int cn = chn + 1;
            if (cn < 8){
                CPA(dAhi + nxt*ABUF, g_basesHI + (size_t)(x0+row)*MODE + cn*16 + ch*8);
                CPA(dAlo + nxt*ABUF, g_basesLO + (size_t)(x0+row)*MODE + cn*16 + ch*8);
                pbn = pk4(*(const float4*)&g_y[((size_t)b*DIMC + ro)*MODE + cn*16 + q*4]);
            } else {
                CPA(dAhi + nxt*ABUF, hxHI + ((size_t)b*NXS + x0 + row)*DIMC + (cn-8)*16 + ch*8);
                CPA(dAlo + nxt*ABUF, hxLO + ((size_t)b*NXS + x0 + row)*DIMC + (cn-8)*16 + ch*8);
                pbn = pk4(*(const float4*)&Wconv_l[(size_t)ro*DIMC + (cn-8)*16 + q*4]);
            }
            CPC();
            CPW1();
        } else CPW0();
        __syncthreads();
        unsigned offA = cur*ABUF + loff;
        unsigned offB = cur*BBUF + loff;
        unsigned Ah[4][4], Al[4][4], Bh[4], Bl[4];
        #pragma unroll
        for (int tm = 0; tm < 4; tm++){
            LDSM4(Ah[tm], bAhi + offA + (wm*64 + tm*16)*48);
            LDSM4(Al[tm], bAlo + offA + (wm*64 + tm*16)*48);
        }
        LDSM4(Bh, bBhi + offB + (wn*16)*48);
        LDSM4(Bl, bBlo + offB + (wn*16)*48);
        #pragma unroll
        for (int tm = 0; tm < 4; tm++)
            #pragma unroll
            for (int tn = 0; tn < 2; tn++){
                unsigned bh[2] = {Bh[tn], Bh[tn+2]};
                unsigned bl[2] = {Bl[tn], Bl[tn+2]};
                MMA(c[tm][tn], Ah[tm], bh);
                MMA(c[tm][tn], Al[tm], bh);
                MMA(c[tm][tn], Ah[tm], bl);
            }
        if (chn + 1 < nch){
            *(uint2*)&Bhw[nxt*(BBUF/4) + ro*12 + q*2] = up_hi(pbn);
            *(uint2*)&Blw[nxt*(BBUF/4) + ro*12 + q*2] = up_lo(pbn);
        }
        __syncthreads();
    }
    // pool becomes Csm
    #pragma unroll
    for (int tm = 0; tm < 4; tm++)
        #pragma unroll
        for (int tn = 0; tn < 2; tn++){
            int xr = wm*64 + tm*16 + g;
            int oc = wn*16 + tn*8 + t*2;
            Csm[oc][xr]     = c[tm][tn][0]; Csm[oc+1][xr]   = c[tm][tn][1];
            Csm[oc][xr+8]   = c[tm][tn][2]; Csm[oc+1][xr+8] = c[tm][tn][3];
        }
    __syncthreads();
    {
        int o = tid >> 2;
        float bias = tail3 ? g_bias0[o] : biasv[o];
        float w0 = 0.f, w1 = 0.f, w2c = 0.f;
        if (tail3){ w0 = g_Wc0T[o]; w1 = g_Wc0T[64+o]; w2c = g_Wc0T[128+o]; }
        #pragma unroll 4
        for (int j = 0; j < 32; j++){
            int xr = (tid & 3)*32 + j;
            float v = Csm[o][xr] + bias;
            if (tail3){
                int gx = x0 + xr;
                v += g_xT[((size_t)b*IN_DIM + 0)*NXS + gx]*w0
                   + g_xT[((size_t)b*IN_DIM + 1)*NXS + gx]*w1
                   + g_xT[((size_t)b*IN_DIM + 2)*NXS + gx]*w2c;
            }
            if (!is_last) CsmU[o][xr] = pk_split(gelu_f(v));
            else          Csm[o][xr] = v;
        }
    }
    __syncthreads();
    if (!is_last){
        for (int i = tid; i < 64*64; i += 256){
            int cc = i >> 6, xp = i & 63;
            unsigned u0 = CsmU[cc][2*xp], u1 = CsmU[cc][2*xp+1];
            unsigned hi = (u0 >> 16) | (u1 & 0xFFFF0000u);
            unsigned lo = (u0 & 0xFFFFu) | (u1 << 16);
            size_t base = (size_t)(b*DIMC + cc)*NXS + x0;
            ((unsigned*)(hcoHI + base))[xp] = hi;
            ((unsigned*)(hcoLO + base))[xp] = lo;
        }
        for (int i = tid; i < 128*32; i += 256){
            int xx = i >> 5, cp = i & 31;
            unsigned u0 = CsmU[2*cp][xx], u1 = CsmU[2*cp+1][xx];
            unsigned hi = (u0 >> 16) | (u1 & 0xFFFF0000u);
            unsigned lo = (u0 & 0xFFFFu) | (u1 << 16);
            size_t base = ((size_t)b*NXS + x0 + xx)*DIMC;
            ((unsigned*)(hxoHI + base))[cp] = hi;
            ((unsigned*)(hxoLO + base))[cp] = lo;
        }
        return;
    }
    // ---- last layer: fused fc1(gelu)+fc2 (FFMA epilogue) ----
    int xl4 = (tid & 31) * 4;
    int fbq = (tid >> 5) * 16;
    float zacc[4][16] = {};
    for (int c0 = 0; c0 < 64; c0 += 16){
        int kk = tid >> 4, c4 = tid & 15;
        float4 w0v = *(const float4*)&W1[(size_t)(c0 + kk)*FCD + c4*4];
        float4 w1v = *(const float4*)&W1[(size_t)(c0 + kk)*FCD + (c4+16)*4];
        __syncthreads();
        *(float4*)&W1s[kk][c4*4]      = w0v;
        *(float4*)&W1s[kk][(c4+16)*4] = w1v;
        __syncthreads();
        #pragma unroll
        for (int cc = 0; cc < 16; cc++){
            float4 a4 = *(const float4*)&Csm[c0 + cc][xl4];
            #pragma unroll
            for (int qq = 0; qq < 16; qq++){
                float bb = W1s[cc][fbq + qq];
                zacc[0][qq] += a4.x * bb;
                zacc[1][qq] += a4.y * bb;
                zacc[2][qq] += a4.z * bb;
                zacc[3][qq] += a4.w * bb;
            }
        }
    }
    float part[4] = {0.f,0.f,0.f,0.f};
    #pragma unroll
    for (int qq = 0; qq < 16; qq++){
        float b1v = b1[fbq + qq];
        float w2v = W2[fbq + qq];
        #pragma unroll
        for (int z = 0; z < 4; z++)
            part[z] += gelu_f(zacc[z][qq] + b1v) * w2v;
    }
    __syncthreads();
    float* scratch = &W1s[0][0];
    *(float4*)&scratch[(tid >> 5)*128 + xl4] = make_float4(part[0],part[1],part[2],part[3]);
    __syncthreads();
    if (tid < 128){
        float s = b2[0];
        #pragma unroll
        for (int w = 0; w < 8; w++) s += scratch[w*128 + tid];
        out[(size_t)b*NXS + x0 + tid] = s;
    }
}

// ---------------------------------------------------------------------------
extern "C" void kernel_launch(void* const* d_in, const int* in_sizes, int n_in,
                              void* d_out, int out_size){
    (void)in_sizes; (void)n_in; (void)out_size;
    const float* x      = (const float*)d_in[0];
    const float* bases  = (const float*)d_in[1];
    const float* wbases = (const float*)d_in[2];
    const float* product= (const float*)d_in[3];
    const float* Do     = (const float*)d_in[4];
    const float* Di     = (const float*)d_in[5];
    const float* A      = (const float*)d_in[6];
    const float* Bm     = (const float*)d_in[7];
    const float* W_sp   = (const float*)d_in[8];
    const float* W_conv = (const float*)d_in[9];
    const float* b_conv = (const float*)d_in[10];
    const float* W0     = (const float*)d_in[11];
    const float* b0     = (const float*)d_in[12];
    const float* W1     = (const float*)d_in[13];
    const float* b1     = (const float*)d_in[14];
    const float* W2     = (const float*)d_in[15];
    const float* b2     = (const float*)d_in[16];
    float* out = (float*)d_out;

    ushortx *hcHa,*hcLa,*hcHb,*hcLb,*hxHa,*hxLa,*hxHb,*hxLb;
    cudaGetSymbolAddress((void**)&hcHa, g_hcHIa);
    cudaGetSymbolAddress((void**)&hcLa, g_hcLOa);
    cudaGetSymbolAddress((void**)&hcHb, g_hcHIb);
    cudaGetSymbolAddress((void**)&hcLb, g_hcLOb);
    cudaGetSymbolAddress((void**)&hxHa, g_hxHIa);
    cudaGetSymbolAddress((void**)&hxLa, g_hxLOa);
    cudaGetSymbolAddress((void**)&hxHb, g_hxHIb);
    cudaGetSymbolAddress((void**)&hxLb, g_hxLOb);

    k_basesP<<<(NXS*MODE)/256, 256>>>(bases);
    k_wbTP<<<dim3(NXS/32, MODE/32), dim3(32,8)>>>(wbases);
    k_buildHT<<<dim3(NJ, MODE), MODE>>>(Do, Di, product, A, Bm);
    k_xT<<<(BSZ*NXS*IN_DIM)/256, 256>>>(x);
    k_prep0<<<1, DIMC>>>(W_conv, W0, b0, b_conv);

    // ---- layer 0 (h0 never materialized) ----
    k_T<<<dim3(BSZ, T_SPLITS), MODE>>>(wbases);
    k_xh0<<<BSZ, 256>>>(W0, b0);
    k_xh1<<<dim3(BSZ, NJ), 256>>>();
    k_WrT<<<(NJ*DIMC*DIMC)/256, 256>>>(W_sp, 0);
    k_y_part<<<dim3(BSZ, Y_SPLITS), 256>>>();
    k_reduce_y<<<(BSZ*DIMC*MODE)/256, 256>>>();
    k_L_mma<<<dim3(NXS/128, BSZ), 256>>>(hxHa, hxLa, hcHa, hcLa, hxHa, hxLa,
                                         nullptr, nullptr,
                                         W1, b1, W2, b2, out, 1, 0);
    // ---- layers 1,2 ----
    const ushortx *hcH = hcHa, *hcL = hcLa, *hxH = hxHa, *hxL = hxLa;
    ushortx *hcHo = hcHb, *hcLo = hcLb, *hxHo = hxHb, *hxLo = hxLb;
    for (int li = 1; li < N_LAYERS; li++){
        k_xh_mma<<<dim3((BSZ*DIMC)/128, XH_SPLITS), 256>>>(hcH, hcL);
        k_reduce_xh<<<(BSZ*DIMC*MODE)/256, 256>>>();
        k_xh1<<<dim3(BSZ, NJ), 256>>>();
        k_WrT<<<(NJ*DIMC*DIMC)/256, 256>>>(W_sp, li);
        k_y_part<<<dim3(BSZ, Y_SPLITS), 256>>>();
        k_reduce_y<<<(BSZ*DIMC*MODE)/256, 256>>>();
        k_L_mma<<<dim3(NXS/128, BSZ), 256>>>(hxH, hxL, hcHo, hcLo, hxHo, hxLo,
                                             &W_conv[(size_t)li*DIMC*DIMC],
                                             &b_conv[(size_t)li*DIMC],
                                             W1, b1, W2, b2, out,
                                             0, (li == N_LAYERS-1) ? 1 : 0);
        const ushortx* t1 = hcH; hcH = hcHo; hcHo = (ushortx*)t1;
        const ushortx* t2 = hcL; hcL = hcLo; hcLo = (ushortx*)t2;
        const ushortx* t3 = hxH; hxH = hxHo; hxHo = (ushortx*)t3;
        const ushortx* t4 = hxL; hxL = hxLo; hxLo = (ushortx*)t4;
    }
}

// round 9
// speedup vs baseline: 1.4679x; 1.0548x over previous
#include <cuda_runtime.h>
#include <cuda_bf16.h>
#include <math.h>
#include <stdint.h>

#define BSZ 32
#define NXS 16384
#define IN_DIM 3
#define DIMC 64
#define NJ 16
#define MODE 128
#define RANKR 4
#define FCD 128
#define N_LAYERS 3
#define XH_SPLITS 8
#define Y_SPLITS 8
#define T_SPLITS 8

typedef unsigned short ushortx;

__device__ ushortx g_hcHIa[(size_t)BSZ*DIMC*NXS];
__device__ ushortx g_hcLOa[(size_t)BSZ*DIMC*NXS];
__device__ ushortx g_hcHIb[(size_t)BSZ*DIMC*NXS];
__device__ ushortx g_hcLOb[(size_t)BSZ*DIMC*NXS];
__device__ ushortx g_hxHIa[(size_t)BSZ*NXS*DIMC];
__device__ ushortx g_hxLOa[(size_t)BSZ*NXS*DIMC];
__device__ ushortx g_hxHIb[(size_t)BSZ*NXS*DIMC];
__device__ ushortx g_hxLOb[(size_t)BSZ*NXS*DIMC];
__device__ ushortx g_wbTHI[(size_t)MODE*NXS];
__device__ ushortx g_wbTLO[(size_t)MODE*NXS];
__device__ ushortx g_basesHI[(size_t)NXS*MODE];
__device__ ushortx g_basesLO[(size_t)NXS*MODE];
__device__ ushortx g_W1THI[FCD*DIMC];   // [f][c]
__device__ ushortx g_W1TLO[FCD*DIMC];
__device__ float g_xT[BSZ*IN_DIM*NXS];
__device__ float g_HT[NJ*MODE*MODE];
__device__ float g_xh [BSZ*DIMC*MODE];
__device__ float g_xhp[XH_SPLITS*BSZ*DIMC*MODE];
__device__ float g_xh1[BSZ*DIMC*NJ*MODE];
__device__ float g_WrT[NJ*DIMC*DIMC];
__device__ float g_y  [BSZ*DIMC*MODE];
__device__ float g_yp [Y_SPLITS*BSZ*DIMC*MODE];
__device__ float g_Tp [T_SPLITS*BSZ*4*MODE];
__device__ float g_Wc0T[IN_DIM*DIMC];
__device__ float g_bias0[DIMC];

__device__ __forceinline__ float gelu_f(float v){
    return 0.5f * v * (1.0f + erff(v * 0.70710678118654752440f));
}
__device__ __forceinline__ void split2(float x, ushortx& hi, ushortx& lo){
    __nv_bfloat16 h = __float2bfloat16(x);
    hi = __bfloat16_as_ushort(h);
    lo = __bfloat16_as_ushort(__float2bfloat16(x - __bfloat162float(h)));
}
__device__ __forceinline__ unsigned pk_split(float x){
    ushortx hi, lo; split2(x, hi, lo);
    return ((unsigned)hi << 16) | (unsigned)lo;
}
__device__ __forceinline__ uint4 pk4(float4 f){
    return make_uint4(pk_split(f.x), pk_split(f.y), pk_split(f.z), pk_split(f.w));
}
__device__ __forceinline__ uint2 up_hi(uint4 u){
    return make_uint2((u.x >> 16) | (u.y & 0xFFFF0000u), (u.z >> 16) | (u.w & 0xFFFF0000u));
}
__device__ __forceinline__ uint2 up_lo(uint4 u){
    return make_uint2((u.x & 0xFFFFu) | (u.y << 16), (u.z & 0xFFFFu) | (u.w << 16));
}
#define MMA(c,a,b) asm volatile( \
    "mma.sync.aligned.m16n8k16.row.col.f32.bf16.bf16.f32 " \
    "{%0,%1,%2,%3}, {%4,%5,%6,%7}, {%8,%9}, {%0,%1,%2,%3};" \
    : "+f"((c)[0]), "+f"((c)[1]), "+f"((c)[2]), "+f"((c)[3]) \
    : "r"((a)[0]), "r"((a)[1]), "r"((a)[2]), "r"((a)[3]), "r"((b)[0]), "r"((b)[1]))
#define LDSM4(f,addr) asm volatile( \
    "ldmatrix.sync.aligned.m8n8.x4.shared.b16 {%0,%1,%2,%3}, [%4];" \
    : "=r"((f)[0]), "=r"((f)[1]), "=r"((f)[2]), "=r"((f)[3]) : "r"(addr))
#define CPA(dst,src) asm volatile("cp.async.cg.shared.global [%0], [%1], 16;" :: "r"(dst), "l"(src))
#define CPC() asm volatile("cp.async.commit_group;" ::: "memory")
#define CPW1() asm volatile("cp.async.wait_group 1;" ::: "memory")
#define CPW0() asm volatile("cp.async.wait_group 0;" ::: "memory")

// ---------------- prep ----------------
__global__ void k_xT(const float* __restrict__ x){
    int i = blockIdx.x * 256 + threadIdx.x;
    int d = i % 3, t = i / 3;
    g_xT[((size_t)(t >> 14)*IN_DIM + d)*NXS + (t & (NXS-1))] = x[i];
}
__global__ void k_basesP(const float* __restrict__ bases){
    int i = blockIdx.x * 256 + threadIdx.x;
    split2(bases[i], g_basesHI[i], g_basesLO[i]);
}
__global__ void k_wbTP(const float* __restrict__ wb){
    __shared__ float t[32][33];
    int x0 = blockIdx.x * 32, k0 = blockIdx.y * 32;
    for (int i = threadIdx.y; i < 32; i += 8)
        t[i][threadIdx.x] = wb[(size_t)(x0 + i)*MODE + k0 + threadIdx.x];
    __syncthreads();
    for (int i = threadIdx.y; i < 32; i += 8){
        size_t o = (size_t)(k0 + i)*NXS + x0 + threadIdx.x;
        split2(t[threadIdx.x][i], g_wbTHI[o], g_wbTLO[o]);
    }
}
__global__ void k_W1TP(const float* __restrict__ W1){
    int i = blockIdx.x * 256 + threadIdx.x;  // < 8192
    int f = i >> 6, c = i & 63;
    split2(W1[c*FCD + f], g_W1THI[i], g_W1TLO[i]);
}
__global__ void k_buildHT(const float* __restrict__ Do, const float* __restrict__ Di,
                          const float* __restrict__ pr, const float* __restrict__ A,
                          const float* __restrict__ Bm){
    int j = blockIdx.x, l = blockIdx.y, k = threadIdx.x;
    float s = Do[j*MODE + k] * Di[j*MODE + l] * pr[k*MODE + l];
    #pragma unroll
    for (int r = 0; r < RANKR; r++)
        s += A[(j*RANKR + r)*MODE + k] * Bm[(j*RANKR + r)*MODE + l];
    g_HT[((size_t)j*MODE + l)*MODE + k] = s;
}
__global__ void k_prep0(const float* __restrict__ W_conv, const float* __restrict__ W0,
                        const float* __restrict__ b0, const float* __restrict__ b_conv){
    int o = threadIdx.x;
    float w0s = 0.f, w1s = 0.f, w2s = 0.f, bb = b_conv[o];
    for (int c = 0; c < DIMC; c++){
        float wc = W_conv[o*DIMC + c];
        w0s += wc*W0[c]; w1s += wc*W0[DIMC+c]; w2s += wc*W0[2*DIMC+c];
        bb  += wc*b0[c];
    }
    g_Wc0T[o] = w0s; g_Wc0T[64+o] = w1s; g_Wc0T[128+o] = w2s; g_bias0[o] = bb;
}
__global__ void k_T(const float* __restrict__ wbases){
    int b = blockIdx.x, s = blockIdx.y;
    int x0 = s * (NXS / T_SPLITS);
    int k = threadIdx.x;
    __shared__ float xs[3][128];
    float a0=0.f, a1=0.f, a2=0.f, a3=0.f;
    for (int xt = 0; xt < (NXS/T_SPLITS)/128; xt++){
        __syncthreads();
        xs[0][k] = g_xT[((size_t)b*IN_DIM + 0)*NXS + x0 + xt*128 + k];
        xs[1][k] = g_xT[((size_t)b*IN_DIM + 1)*NXS + x0 + xt*128 + k];
        xs[2][k] = g_xT[((size_t)b*IN_DIM + 2)*NXS + x0 + xt*128 + k];
        __syncthreads();
        #pragma unroll 8
        for (int xi = 0; xi < 128; xi++){
            float w = wbases[(size_t)(x0 + xt*128 + xi)*MODE + k];
            a0 += xs[0][xi]*w; a1 += xs[1][xi]*w; a2 += xs[2][xi]*w; a3 += w;
        }
    }
    size_t base = (((size_t)s*BSZ + b)*4)*MODE + k;
    g_Tp[base] = a0; g_Tp[base+MODE] = a1; g_Tp[base+2*MODE] = a2; g_Tp[base+3*MODE] = a3;
}
__global__ void k_xh0(const float* __restrict__ W0, const float* __restrict__ b0){
    int b = blockIdx.x;
    __shared__ float Ts[4][128];
    int tid = threadIdx.x;
    for (int e = tid; e < 4*MODE; e += 256){
        int d = e >> 7, k = e & 127;
        float s = 0.f;
        #pragma unroll
        for (int s8 = 0; s8 < T_SPLITS; s8++)
            s += g_Tp[(((size_t)s8*BSZ + b)*4 + d)*MODE + k];
        Ts[d][k] = s;
    }
    __syncthreads();
    for (int o = tid; o < DIMC*MODE; o += 256){
        int c = o >> 7, k = o & 127;
        g_xh[((size_t)b*DIMC + c)*MODE + k] =
            W0[c]*Ts[0][k] + W0[DIMC+c]*Ts[1][k] + W0[2*DIMC+c]*Ts[2][k] + b0[c]*Ts[3][k];
    }
}

// ===== GEMM1 (mma.sync + cp.async + ldmatrix) =====
__global__ void __launch_bounds__(256) k_xh_mma(const ushortx* __restrict__ hcHI,
                                                const ushortx* __restrict__ hcLO){
    __shared__ __align__(16) unsigned sm[4][2][128][12];
    const int NIT = (NXS/XH_SPLITS)/16;
    int tid = threadIdx.x, lane = tid & 31, wid = tid >> 5;
    int wm = wid >> 2, wn = wid & 3, g = lane >> 2, t = lane & 3;
    int m0 = blockIdx.x * 128;
    int k0 = blockIdx.y * (NXS / XH_SPLITS);
    int row = tid >> 1, ch = tid & 1;
    const ushortx* src[4];
    src[0] = hcHI    + (size_t)(m0+row)*NXS + k0 + ch*8;
    src[1] = hcLO    + (size_t)(m0+row)*NXS + k0 + ch*8;
    src[2] = g_wbTHI + (size_t)row*NXS      + k0 + ch*8;
    src[3] = g_wbTLO + (size_t)row*NXS      + k0 + ch*8;
    unsigned dstb[4], bA[4];
    #pragma unroll
    for (int a = 0; a < 4; a++){
        dstb[a] = (unsigned)__cvta_generic_to_shared(&sm[a][0][row][ch*4]);
        bA[a]   = (unsigned)__cvta_generic_to_shared(&sm[a][0][0][0]);
    }
    const unsigned BUFO = 128*12*4;
    unsigned loff = (lane & 15)*48 + (lane >> 4)*16;
    float c[4][4][4] = {};
    #pragma unroll
    for (int a = 0; a < 4; a++) CPA(dstb[a], src[a]);
    CPC();
    for (int it = 0; it < NIT; it++){
        int cur = it & 1, nxt = cur ^ 1;
        if (it + 1 < NIT){
            #pragma unroll
            for (int a = 0; a < 4; a++) CPA(dstb[a] + nxt*BUFO, src[a] + (size_t)(it+1)*16);
            CPC();
            CPW1();
        } else CPW0();
        __syncthreads();
        unsigned off = cur*BUFO + loff;
        unsigned Ah[4][4], Al[4][4], Bh[2][4], Bl[2][4];
        #pragma unroll
        for (int tm = 0; tm < 4; tm++){
            LDSM4(Ah[tm], bA[0] + off + (wm*64 + tm*16)*48);
            LDSM4(Al[tm], bA[1] + off + (wm*64 + tm*16)*48);
        }
        #pragma unroll
        for (int p = 0; p < 2; p++){
            LDSM4(Bh[p], bA[2] + off + (wn*32 + p*16)*48);
            LDSM4(Bl[p], bA[3] + off + (wn*32 + p*16)*48);
        }
        #pragma unroll
        for (int tm = 0; tm < 4; tm++)
            #pragma unroll
            for (int tn = 0; tn < 4; tn++){
                int p = tn >> 1, e = tn & 1;
                unsigned bh[2] = {Bh[p][e], Bh[p][e+2]};
                unsigned bl[2] = {Bl[p][e], Bl[p][e+2]};
                MMA(c[tm][tn], Ah[tm], bh);
                MMA(c[tm][tn], Al[tm], bh);
                MMA(c[tm][tn], Ah[tm], bl);
            }
        __syncthreads();
    }
    float* dst = &g_xhp[(size_t)blockIdx.y*(BSZ*DIMC*MODE)];
    #pragma unroll
    for (int tm = 0; tm < 4; tm++)
        #pragma unroll
        for (int tn = 0; tn < 4; tn++){
            int m = m0 + wm*64 + tm*16 + g;
            int n = wn*32 + tn*8 + t*2;
            *(float2*)&dst[(size_t)m*MODE + n]     = make_float2(c[tm][tn][0], c[tm][tn][1]);
            *(float2*)&dst[(size_t)(m+8)*MODE + n] = make_float2(c[tm][tn][2], c[tm][tn][3]);
        }
}
__global__ void k_reduce_xh(){
    int i = blockIdx.x * 256 + threadIdx.x;
    float s = 0.f;
    #pragma unroll
    for (int k = 0; k < XH_SPLITS; k++) s += g_xhp[(size_t)k*(BSZ*DIMC*MODE) + i];
    g_xh[i] = s;
}

// ================= mid pipeline (fp32, known-good) =================
__global__ void __launch_bounds__(256) k_xh1(){
    int b = blockIdx.x, j = blockIdx.y;
    __shared__ float xs[64][128];
    __shared__ float Bs[16][128];
    int tid = threadIdx.x, rg = tid >> 5, cg = tid & 31;
    {
        const float4* src = (const float4*)&g_xh[(size_t)b*DIMC*MODE];
        float4* dst = (float4*)&xs[0][0];
        for (int i = tid; i < 64*128/4; i += 256) dst[i] = src[i];
    }
    float acc[8][4] = {};
    for (int kt = 0; kt < 8; kt++){
        int kkB = tid >> 4, n8 = (tid & 15) * 8;
        const float* bsrc = &g_HT[((size_t)j*MODE + kt*16 + kkB)*MODE + n8];
        float4 bv0 = *(const float4*)bsrc, bv1 = *(const float4*)(bsrc + 4);
        __syncthreads();
        *(float4*)&Bs[kkB][n8] = bv0; *(float4*)&Bs[kkB][n8+4] = bv1;
        __syncthreads();
        #pragma unroll
        for (int kk = 0; kk < 16; kk++){
            int l = kt*16 + kk;
            float a_[8];
            #pragma unroll
            for (int i_ = 0; i_ < 8; i_++) a_[i_] = xs[rg*8 + i_][l];
            float4 bv_ = *(const float4*)&Bs[kk][cg*4];
            #pragma unroll
            for (int i_ = 0; i_ < 8; i_++){
                acc[i_][0] += a_[i_]*bv_.x; acc[i_][1] += a_[i_]*bv_.y;
                acc[i_][2] += a_[i_]*bv_.z; acc[i_][3] += a_[i_]*bv_.w;
            }
        }
    }
    #pragma unroll
    for (int i = 0; i < 8; i++)
        *(float4*)&g_xh1[((size_t)b*(DIMC*NJ) + (size_t)(rg*8 + i)*NJ + j)*MODE + cg*4] =
            make_float4(acc[i][0], acc[i][1], acc[i][2], acc[i][3]);
}
__global__ void k_WrT(const float* __restrict__ W_sp, int li){
    int idx = blockIdx.x * 256 + threadIdx.x;
    int o = idx & 63, p = idx >> 6;
    g_WrT[(size_t)p*DIMC + o] = W_sp[(((size_t)li*DIMC + (p >> 4))*DIMC + o)*NJ + (p & 15)];
}
__global__ void __launch_bounds__(256) k_y_part(){
    int b = blockIdx.x, s = blockIdx.y;
    int p0 = s * 128;
    __shared__ float As[16][65];
    __shared__ float Bs[16][128];
    int tid = threadIdx.x, rg = tid >> 5, cg = tid & 31;
    float acc[8][4] = {};
    for (int kt = 0; kt < 8; kt++){
        int kkA = tid >> 4, o4 = (tid & 15) * 4;
        float4 av = *(const float4*)&g_WrT[(size_t)(p0 + kt*16 + kkA)*DIMC + o4];
        int n8 = (tid & 15) * 8;
        const float* bsrc = &g_xh1[((size_t)b*(DIMC*NJ) + p0 + kt*16 + kkA)*MODE + n8];
        float4 bv0 = *(const float4*)bsrc, bv1 = *(const float4*)(bsrc + 4);
        __syncthreads();
        As[kkA][o4]=av.x; As[kkA][o4+1]=av.y; As[kkA][o4+2]=av.z; As[kkA][o4+3]=av.w;
        *(float4*)&Bs[kkA][n8] = bv0; *(float4*)&Bs[kkA][n8+4] = bv1;
        __syncthreads();
        #pragma unroll
        for (int kk = 0; kk < 16; kk++){
            float a_[8];
            #pragma unroll
            for (int i_ = 0; i_ < 8; i_++) a_[i_] = As[kk][rg*8 + i_];
            float4 bv_ = *(const float4*)&Bs[kk][cg*4];
            #pragma unroll
            for (int i_ = 0; i_ < 8; i_++){
                acc[i_][0] += a_[i_]*bv_.x; acc[i_][1] += a_[i_]*bv_.y;
                acc[i_][2] += a_[i_]*bv_.z; acc[i_][3] += a_[i_]*bv_.w;
            }
        }
    }
    #pragma unroll
    for (int i = 0; i < 8; i++)
        *(float4*)&g_yp[(size_t)s*(BSZ*DIMC*MODE) + ((size_t)b*DIMC + rg*8 + i)*MODE + cg*4] =
            make_float4(acc[i][0], acc[i][1], acc[i][2], acc[i][3]);
}
__global__ void k_reduce_y(){
    int i = blockIdx.x * 256 + threadIdx.x;
    float s = 0.f;
    #pragma unroll
    for (int k = 0; k < Y_SPLITS; k++) s += g_yp[(size_t)k*(BSZ*DIMC*MODE) + i];
    g_y[i] = s;
}

// ===== GEMM2 + tensorized fc1 epilogue =====
#define CSW 132
#define AHI_OFF 0
#define ALO_OFF 12288
#define BHI_OFF 24576
#define BLO_OFF 30720
#define ABUF 6144
#define BBUF 3072
#define FAHI 36864
#define FALO 43008
#define FBHI 49152
#define FBLO 55296
#define LSM_LAST 61440
#define LSM_MID  36864
__global__ void __launch_bounds__(256) k_L_mma(
    const ushortx* __restrict__ hxHI, const ushortx* __restrict__ hxLO,
    ushortx* __restrict__ hcoHI, ushortx* __restrict__ hcoLO,
    ushortx* __restrict__ hxoHI, ushortx* __restrict__ hxoLO,
    const float* __restrict__ Wconv_l, const float* __restrict__ biasv,
    const float* __restrict__ b1, const float* __restrict__ W2,
    const float* __restrict__ b2,
    float* __restrict__ out, int tail3, int is_last)
{
    extern __shared__ __align__(16) char pool[];
    float (*Csm)[CSW]  = (float(*)[CSW])pool;
    unsigned (*CsmU)[CSW] = (unsigned(*)[CSW])pool;

    int tid = threadIdx.x, lane = tid & 31, wid = tid >> 5;
    int wm = wid >> 2, wn = wid & 3, g = lane >> 2, t = lane & 3;
    int b = blockIdx.y;
    int x0 = blockIdx.x * 128;
    int row = tid >> 1, ch = tid & 1;
    int ro = tid >> 2, q = tid & 3;
    int nch = tail3 ? 8 : 12;

    unsigned sbase = (unsigned)__cvta_generic_to_shared(pool);
    unsigned dAhi = sbase + AHI_OFF + row*48 + ch*16;
    unsigned dAlo = dAhi + (ALO_OFF - AHI_OFF);
    unsigned bAhi = sbase + AHI_OFF, bAlo = sbase + ALO_OFF;
    unsigned bBhi = sbase + BHI_OFF, bBlo = sbase + BLO_OFF;
    unsigned* Bhw = (unsigned*)(pool + BHI_OFF);
    unsigned* Blw = (unsigned*)(pool + BLO_OFF);
    unsigned loff = (lane & 15)*48 + (lane >> 4)*16;

    float c[4][2][4] = {};
    CPA(dAhi, g_basesHI + (size_t)(x0+row)*MODE + ch*8);
    CPA(dAlo, g_basesLO + (size_t)(x0+row)*MODE + ch*8);
    CPC();
    {
        uint4 pb = pk4(*(const float4*)&g_y[((size_t)b*DIMC + ro)*MODE + q*4]);
        *(uint2*)&Bhw[ro*12 + q*2] = up_hi(pb);
        *(uint2*)&Blw[ro*12 + q*2] = up_lo(pb);
    }
    for (int chn = 0; chn < nch; chn++){
        int cur = chn & 1, nxt = cur ^ 1;
        uint4 pbn;
        if (chn + 1 < nch){
            int cn = chn + 1;
            if (cn < 8){
                CPA(dAhi + nxt*ABUF, g_basesHI + (size_t)(x0+row)*MODE + cn*16 + ch*8);
                CPA(dAlo + nxt*ABUF, g_basesLO + (size_t)(x0+row)*MODE + cn*16 + ch*8);
                pbn = pk4(*(const float4*)&g_y[((size_t)b*DIMC + ro)*MODE + cn*16 + q*4]);
            } else {
                CPA(dAhi + nxt*ABUF, hxHI + ((size_t)b*NXS + x0 + row)*DIMC + (cn-8)*16 + ch*8);
                CPA(dAlo + nxt*ABUF, hxLO + ((size_t)b*NXS + x0 + row)*DIMC + (cn-8)*16 + ch*8);
                pbn = pk4(*(const float4*)&Wconv_l[(size_t)ro*DIMC + (cn-8)*16 + q*4]);
            }
            CPC();
            CPW1();
        } else CPW0();
        __syncthreads();
        unsigned offA = cur*ABUF + loff;
        unsigned offB = cur*BBUF + loff;
        unsigned Ah[4][4], Al[4][4], Bh[4], Bl[4];
        #pragma unroll
        for (int tm = 0; tm < 4; tm++){
            LDSM4(Ah[tm], bAhi + offA + (wm*64 + tm*16)*48);
            LDSM4(Al[tm], bAlo + offA + (wm*64 + tm*16)*48);
        }
        LDSM4(Bh, bBhi + offB + (wn*16)*48);
        LDSM4(Bl, bBlo + offB + (wn*16)*48);
        #pragma unroll
        for (int tm = 0; tm < 4; tm++)
            #pragma unroll
            for (int tn = 0; tn < 2; tn++){
                unsigned bh[2] = {Bh[tn], Bh[tn+2]};
                unsigned bl[2] = {Bl[tn], Bl[tn+2]};
                MMA(c[tm][tn], Ah[tm], bh);
                MMA(c[tm][tn], Al[tm], bh);
                MMA(c[tm][tn], Ah[tm], bl);
            }
        if (chn + 1 < nch){
            *(uint2*)&Bhw[nxt*(BBUF/4) + ro*12 + q*2] = up_hi(pbn);
            *(uint2*)&Blw[nxt*(BBUF/4) + ro*12 + q*2] = up_lo(pbn);
        }
        __syncthreads();
    }
    #pragma unroll
    for (int tm = 0; tm < 4; tm++)
        #pragma unroll
        for (int tn = 0; tn < 2; tn++){
            int xr = wm*64 + tm*16 + g;
            int oc = wn*16 + tn*8 + t*2;
            Csm[oc][xr]     = c[tm][tn][0]; Csm[oc+1][xr]   = c[tm][tn][1];
            Csm[oc][xr+8]   = c[tm][tn][2]; Csm[oc+1][xr+8] = c[tm][tn][3];
        }
    __syncthreads();
    {
        int o = tid >> 2;
        float bias = tail3 ? g_bias0[o] : biasv[o];
        float w0 = 0.f, w1 = 0.f, w2c = 0.f;
        if (tail3){ w0 = g_Wc0T[o]; w1 = g_Wc0T[64+o]; w2c = g_Wc0T[128+o]; }
        #pragma unroll 4
        for (int j = 0; j < 32; j++){
            int xr = (tid & 3)*32 + j;
            float v = Csm[o][xr] + bias;
            if (tail3){
                int gx = x0 + xr;
                v += g_xT[((size_t)b*IN_DIM + 0)*NXS + gx]*w0
                   + g_xT[((size_t)b*IN_DIM + 1)*NXS + gx]*w1
                   + g_xT[((size_t)b*IN_DIM + 2)*NXS + gx]*w2c;
            }
            if (!is_last) CsmU[o][xr] = pk_split(gelu_f(v));
            else          Csm[o][xr] = v;
        }
    }
    __syncthreads();
    if (!is_last){
        for (int i = tid; i < 64*64; i += 256){
            int cc = i >> 6, xp = i & 63;
            unsigned u0 = CsmU[cc][2*xp], u1 = CsmU[cc][2*xp+1];
            unsigned hi = (u0 >> 16) | (u1 & 0xFFFF0000u);
            unsigned lo = (u0 & 0xFFFFu) | (u1 << 16);
            size_t base = (size_t)(b*DIMC + cc)*NXS + x0;
            ((unsigned*)(hcoHI + base))[xp] = hi;
            ((unsigned*)(hcoLO + base))[xp] = lo;
        }
        for (int i = tid; i < 128*32; i += 256){
            int xx = i >> 5, cp = i & 31;
            unsigned u0 = CsmU[2*cp][xx], u1 = CsmU[2*cp+1][xx];
            unsigned hi = (u0 >> 16) | (u1 & 0xFFFF0000u);
            unsigned lo = (u0 & 0xFFFFu) | (u1 << 16);
            size_t base = ((size_t)b*NXS + x0 + xx)*DIMC;
            ((unsigned*)(hxoHI + base))[cp] = hi;
            ((unsigned*)(hxoLO + base))[cp] = lo;
        }
        return;
    }

    // ---- last layer: fc1 via mma (z[x,f] = sum_c h'[x,c] W1[c,f]) ----
    float c2[4][4][4] = {};
    int hh_ = tid & 1, xr_ = tid >> 1;
    for (int ks = 0; ks < 4; ks++){
        {   // stage B2 slab (W1T rows f, cols c-slab) via cp.async
            CPA(sbase + FBHI + row*48 + hh_*16, g_W1THI + row*64 + ks*16 + hh_*8);
            CPA(sbase + FBLO + row*48 + hh_*16, g_W1TLO + row*64 + ks*16 + hh_*8);
            CPC();
        }
        {   // pack A2 slab (h' from Csm, transpose c-major -> x rows)
            unsigned uh[4], ul[4];
            #pragma unroll
            for (int j = 0; j < 4; j++){
                ushortx h0,l0,h1,l1;
                split2(Csm[ks*16 + hh_*8 + 2*j][xr_], h0, l0);
                split2(Csm[ks*16 + hh_*8 + 2*j+1][xr_], h1, l1);
                uh[j] = (unsigned)h0 | ((unsigned)h1 << 16);
                ul[j] = (unsigned)l0 | ((unsigned)l1 << 16);
            }
            *(uint4*)(pool + FAHI + xr_*48 + hh_*16) = make_uint4(uh[0],uh[1],uh[2],uh[3]);
            *(uint4*)(pool + FALO + xr_*48 + hh_*16) = make_uint4(ul[0],ul[1],ul[2],ul[3]);
        }
        CPW0();
        __syncthreads();
        unsigned Ah[4][4], Al[4][4], Bh[2][4], Bl[2][4];
        #pragma unroll
        for (int tm = 0; tm < 4; tm++){
            LDSM4(Ah[tm], sbase + FAHI + loff + (wm*64 + tm*16)*48);
            LDSM4(Al[tm], sbase + FALO + loff + (wm*64 + tm*16)*48);
        }
        #pragma unroll
        for (int p = 0; p < 2; p++){
            LDSM4(Bh[p], sbase + FBHI + loff + (wn*32 + p*16)*48);
            LDSM4(Bl[p], sbase + FBLO + loff + (wn*32 + p*16)*48);
        }
        #pragma unroll
        for (int tm = 0; tm < 4; tm++)
            #pragma unroll
            for (int tn = 0; tn < 4; tn++){
                int p = tn >> 1, e = tn & 1;
                unsigned bh[2] = {Bh[p][e], Bh[p][e+2]};
                unsigned bl[2] = {Bl[p][e], Bl[p][e+2]};
                MMA(c2[tm][tn], Ah[tm], bh);
                MMA(c2[tm][tn], Al[tm], bh);
                MMA(c2[tm][tn], Ah[tm], bl);
            }
        __syncthreads();
    }
    // gelu-dot with W2 + cross-warp reduction
    float part[4][2] = {};
    #pragma unroll
    for (int tn = 0; tn < 4; tn++){
        int f0 = wn*32 + tn*8 + t*2;
        float b10 = b1[f0], b11 = b1[f0+1];
        float w20 = W2[f0], w21 = W2[f0+1];
        #pragma unroll
        for (int tm = 0; tm < 4; tm++){
            part[tm][0] += gelu_f(c2[tm][tn][0]+b10)*w20 + gelu_f(c2[tm][tn][1]+b11)*w21;
            part[tm][1] += gelu_f(c2[tm][tn][2]+b10)*w20 + gelu_f(c2[tm][tn][3]+b11)*w21;
        }
    }
    float (*red)[16] = (float(*)[16])(pool + FAHI);
    #pragma unroll
    for (int tm = 0; tm < 4; tm++){
        int xr0 = wm*64 + tm*16 + g;
        red[xr0][wn*4 + t]   = part[tm][0];
        red[xr0+8][wn*4 + t] = part[tm][1];
    }
    __syncthreads();
    if (tid < 128){
        float s = b2[0];
        #pragma unroll
        for (int k = 0; k < 16; k++) s += red[tid][k];
        out[(size_t)b*NXS + x0 + tid] = s;
    }
}

// ---------------------------------------------------------------------------
extern "C" void kernel_launch(void* const* d_in, const int* in_sizes, int n_in,
                              void* d_out, int out_size){
    (void)in_sizes; (void)n_in; (void)out_size;
    const float* x      = (const float*)d_in[0];
    const float* bases  = (const float*)d_in[1];
    const float* wbases = (const float*)d_in[2];
    const float* product= (const float*)d_in[3];
    const float* Do     = (const float*)d_in[4];
    const float* Di     = (const float*)d_in[5];
    const float* A      = (const float*)d_in[6];
    const float* Bm     = (const float*)d_in[7];
    const float* W_sp   = (const float*)d_in[8];
    const float* W_conv = (const float*)d_in[9];
    const float* b_conv = (const float*)d_in[10];
    const float* W0     = (const float*)d_in[11];
    const float* b0     = (const float*)d_in[12];
    const float* W1     = (const float*)d_in[13];
    const float* b1     = (const float*)d_in[14];
    const float* W2     = (const float*)d_in[15];
    const float* b2     = (const float*)d_in[16];
    float* out = (float*)d_out;

    cudaFuncSetAttribute(k_L_mma, cudaFuncAttributeMaxDynamicSharedMemorySize, LSM_LAST);

    ushortx *hcHa,*hcLa,*hcHb,*hcLb,*hxHa,*hxLa,*hxHb,*hxLb;
    cudaGetSymbolAddress((void**)&hcHa, g_hcHIa);
    cudaGetSymbolAddress((void**)&hcLa, g_hcLOa);
    cudaGetSymbolAddress((void**)&hcHb, g_hcHIb);
    cudaGetSymbolAddress((void**)&hcLb, g_hcLOb);
    cudaGetSymbolAddress((void**)&hxHa, g_hxHIa);
    cudaGetSymbolAddress((void**)&hxLa, g_hxLOa);
    cudaGetSymbolAddress((void**)&hxHb, g_hxHIb);
    cudaGetSymbolAddress((void**)&hxLb, g_hxLOb);

    k_basesP<<<(NXS*MODE)/256, 256>>>(bases);
    k_wbTP<<<dim3(NXS/32, MODE/32), dim3(32,8)>>>(wbases);
    k_W1TP<<<(FCD*DIMC)/256, 256>>>(W1);
    k_buildHT<<<dim3(NJ, MODE), MODE>>>(Do, Di, product, A, Bm);
    k_xT<<<(BSZ*NXS*IN_DIM)/256, 256>>>(x);
    k_prep0<<<1, DIMC>>>(W_conv, W0, b0, b_conv);

    // ---- layer 0 ----
    k_T<<<dim3(BSZ, T_SPLITS), MODE>>>(wbases);
    k_xh0<<<BSZ, 256>>>(W0, b0);
    k_xh1<<<dim3(BSZ, NJ), 256>>>();
    k_WrT<<<(NJ*DIMC*DIMC)/256, 256>>>(W_sp, 0);
    k_y_part<<<dim3(BSZ, Y_SPLITS), 256>>>();
    k_reduce_y<<<(BSZ*DIMC*MODE)/256, 256>>>();
    k_L_mma<<<dim3(NXS/128, BSZ), 256, LSM_MID>>>(hxHa, hxLa, hcHa, hcLa, hxHa, hxLa,
                                                  nullptr, nullptr,
                                                  b1, W2, b2, out, 1, 0);
    // ---- layers 1,2 ----
    const ushortx *hcH = hcHa, *hcL = hcLa, *hxH = hxHa, *hxL = hxLa;
    ushortx *hcHo = hcHb, *hcLo = hcLb, *hxHo = hxHb, *hxLo = hxLb;
    for (int li = 1; li < N_LAYERS; li++){
        int last = (li == N_LAYERS-1) ? 1 : 0;
        k_xh_mma<<<dim3((BSZ*DIMC)/128, XH_SPLITS), 256>>>(hcH, hcL);
        k_reduce_xh<<<(BSZ*DIMC*MODE)/256, 256>>>();
        k_xh1<<<dim3(BSZ, NJ), 256>>>();
        k_WrT<<<(NJ*DIMC*DIMC)/256, 256>>>(W_sp, li);
        k_y_part<<<dim3(BSZ, Y_SPLITS), 256>>>();
        k_reduce_y<<<(BSZ*DIMC*MODE)/256, 256>>>();
        k_L_mma<<<dim3(NXS/128, BSZ), 256, last ? LSM_LAST : LSM_MID>>>(
                                             hxH, hxL, hcHo, hcLo, hxHo, hxLo,
                                             &W_conv[(size_t)li*DIMC*DIMC],
                                             &b_conv[(size_t)li*DIMC],
                                             b1, W2, b2, out, 0, last);
        const ushortx* t1 = hcH; hcH = hcHo; hcHo = (ushortx*)t1;
        const ushortx* t2 = hcL; hcL = hcLo; hcLo = (ushortx*)t2;
        const ushortx* t3 = hxH; hxH = hxHo; hxHo = (ushortx*)t3;
        const ushortx* t4 = hxL; hxL = hxLo; hxLo = (ushortx*)t4;
    }
}